// round 1
// baseline (speedup 1.0000x reference)
#include <cuda_runtime.h>
#include <cstddef>

// ---------------------------------------------------------------------------
// NTM single step.  Shapes:
// B=256, N=2048, M=64, CS=512, INP=256, OUT=256, ADDR_R=70, ADDR_W=198
// Output tuple flattened in order:
//   out[256,256], memory_new[256,2048,64], h_new[256,512], c_new[256,512],
//   w_read[256,2048], w_write[256,2048], read_vec[256,64]
// ---------------------------------------------------------------------------

#define Bb 256
#define Nn 2048
#define Mm 64
#define CS 512
#define INP 256
#define KG 832      // INP + M + CS   (concat [x | prev_read | h])
#define NG 2048     // 4*CS
#define NRW 268     // ADDR_R + ADDR_W

// output offsets (elements)
#define OFF_OUT 0
#define OFF_MEM 65536
#define OFF_H   33619968
#define OFF_C   33751040
#define OFF_WR  33882112
#define OFF_WW  34406400
#define OFF_RV  34930688

// scratch
__device__ float g_A1[Bb * KG];
__device__ float g_Wg[NG * KG];
__device__ float g_bg[NG];
__device__ float g_gates[Bb * NG];
__device__ float g_Wrw[NRW * CS];
__device__ float g_brw[NRW];
__device__ float g_rw[Bb * NRW];
__device__ float g_sim_r[Bb * Nn];
__device__ float g_sim_w[Bb * Nn];
__device__ float g_A2[Bb * (CS + Mm)];

__device__ __forceinline__ float sigm(float x) { return 1.f / (1.f + expf(-x)); }
__device__ __forceinline__ float softplus(float x) { return x > 20.f ? x : log1pf(expf(x)); }

// ------------------------- prep kernels ------------------------------------

__global__ void prep_weights(const float* __restrict__ Wih, const float* __restrict__ Whh,
                             const float* __restrict__ bih, const float* __restrict__ bhh,
                             const float* __restrict__ Wr,  const float* __restrict__ br,
                             const float* __restrict__ Ww,  const float* __restrict__ bw,
                             float* __restrict__ rv_zero) {
    int idx = blockIdx.x * blockDim.x + threadIdx.x;
    if (idx < NG * KG) {
        int n = idx / KG, k = idx - n * KG;
        g_Wg[idx] = (k < 320) ? Wih[n * 320 + k] : Whh[n * 512 + (k - 320)];
    }
    if (idx < NG) g_bg[idx] = bih[idx] + bhh[idx];
    if (idx < NRW * CS) {
        int r = idx / CS, k = idx - r * CS;
        g_Wrw[idx] = (r < 70) ? Wr[idx] : Ww[(r - 70) * CS + k];
    }
    if (idx < NRW) g_brw[idx] = (idx < 70) ? br[idx] : bw[idx - 70];
    if (idx < Bb * Mm) rv_zero[idx] = 0.f;
}

__global__ void prep_A1(const float* __restrict__ x, const float* __restrict__ prev_read,
                        const float* __restrict__ h) {
    int idx = blockIdx.x * blockDim.x + threadIdx.x;
    if (idx >= Bb * KG) return;
    int b = idx / KG, k = idx - b * KG;
    float v;
    if (k < 256)      v = x[b * 256 + k];
    else if (k < 320) v = prev_read[b * 64 + (k - 256)];
    else              v = h[b * 512 + (k - 320)];
    g_A1[idx] = v;
}

__global__ void prep_A2(const float* __restrict__ h_new, const float* __restrict__ read_vec) {
    int idx = blockIdx.x * blockDim.x + threadIdx.x;
    if (idx >= Bb * (CS + Mm)) return;
    int b = idx / (CS + Mm), k = idx - b * (CS + Mm);
    g_A2[idx] = (k < CS) ? h_new[b * CS + k] : read_vec[b * Mm + (k - CS)];
}

// ------------------------- generic SGEMM  C = A @ W^T + bias ----------------
// C[M,N], A[M,K], W[N,K].  64x64 tile, 256 threads, 4x4 microtile, BK=16.
// Requires M % 64 == 0, K % 16 == 0.  N guarded.

__global__ void sgemm_tn(const float* __restrict__ A, const float* __restrict__ W,
                         const float* __restrict__ bias, float* __restrict__ C,
                         int M, int N, int K) {
    __shared__ float As[16][68];
    __shared__ float Bs[16][68];
    int bm = blockIdx.y * 64, bn = blockIdx.x * 64;
    int tid = threadIdx.x;
    int lr = tid >> 2;             // 0..63
    int lc = (tid & 3) << 2;       // 0,4,8,12
    int tx = tid & 15, ty = tid >> 4;
    float acc[4][4];
#pragma unroll
    for (int i = 0; i < 4; i++)
#pragma unroll
        for (int j = 0; j < 4; j++) acc[i][j] = 0.f;

    int wrow = bn + lr;
    for (int k0 = 0; k0 < K; k0 += 16) {
        float4 av = *(const float4*)(A + (size_t)(bm + lr) * K + k0 + lc);
        As[lc + 0][lr] = av.x; As[lc + 1][lr] = av.y;
        As[lc + 2][lr] = av.z; As[lc + 3][lr] = av.w;
        float4 wv = make_float4(0.f, 0.f, 0.f, 0.f);
        if (wrow < N) wv = *(const float4*)(W + (size_t)wrow * K + k0 + lc);
        Bs[lc + 0][lr] = wv.x; Bs[lc + 1][lr] = wv.y;
        Bs[lc + 2][lr] = wv.z; Bs[lc + 3][lr] = wv.w;
        __syncthreads();
#pragma unroll
        for (int k = 0; k < 16; k++) {
            float4 a4 = *(const float4*)&As[k][ty * 4];
            float4 b4 = *(const float4*)&Bs[k][tx * 4];
            float a[4] = {a4.x, a4.y, a4.z, a4.w};
            float b[4] = {b4.x, b4.y, b4.z, b4.w};
#pragma unroll
            for (int i = 0; i < 4; i++)
#pragma unroll
                for (int j = 0; j < 4; j++) acc[i][j] += a[i] * b[j];
        }
        __syncthreads();
    }
#pragma unroll
    for (int i = 0; i < 4; i++) {
        int row = bm + ty * 4 + i;
#pragma unroll
        for (int j = 0; j < 4; j++) {
            int col = bn + tx * 4 + j;
            if (col < N) C[(size_t)row * N + col] = acc[i][j] + bias[col];
        }
    }
}

// ------------------------- LSTM pointwise ----------------------------------

__global__ void lstm_pw(const float* __restrict__ c_in,
                        float* __restrict__ h_out, float* __restrict__ c_out) {
    int idx = blockIdx.x * blockDim.x + threadIdx.x;
    if (idx >= Bb * CS) return;
    int b = idx >> 9, j = idx & 511;
    const float* g = g_gates + (size_t)b * NG;
    float ig = sigm(g[j]);
    float fg = sigm(g[512 + j]);
    float gg = tanhf(g[1024 + j]);
    float og = sigm(g[1536 + j]);
    float cn = fg * c_in[idx] + ig * gg;
    float hn = og * tanhf(cn);
    c_out[idx] = cn;
    h_out[idx] = hn;
}

// ------------------------- similarity pass (1 read of memory) ---------------
// grid (Nn/64, Bb), block 256.  sim = dot(mem,k) / ((|k|+eps)*(|mem|+eps))

__global__ void sim_kernel(const float* __restrict__ mem) {
    int b = blockIdx.y;
    int n0 = blockIdx.x * 64;
    __shared__ float kr[64], kw[64];
    __shared__ float nrm[2];
    int t = threadIdx.x;
    const float* base = g_rw + (size_t)b * NRW;
    if (t < 64)       kr[t] = base[t];
    else if (t < 128) kw[t - 64] = base[70 + (t - 64)];
    __syncthreads();
    if (t == 0) {
        float s = 0.f;
        for (int i = 0; i < 64; i++) s += kr[i] * kr[i];
        nrm[0] = sqrtf(s) + 1e-8f;
    } else if (t == 32) {
        float s = 0.f;
        for (int i = 0; i < 64; i++) s += kw[i] * kw[i];
        nrm[1] = sqrtf(s) + 1e-8f;
    }
    __syncthreads();
    int mg = t & 15, rg = t >> 4;
    float4 kr4 = *(const float4*)&kr[mg * 4];
    float4 kw4 = *(const float4*)&kw[mg * 4];
#pragma unroll
    for (int i = 0; i < 4; i++) {
        int n = n0 + i * 16 + rg;
        size_t ro = (size_t)b * Nn + n;
        float4 m4 = *(const float4*)(mem + ro * 64 + mg * 4);
        float dr = m4.x * kr4.x + m4.y * kr4.y + m4.z * kr4.z + m4.w * kr4.w;
        float dw = m4.x * kw4.x + m4.y * kw4.y + m4.z * kw4.z + m4.w * kw4.w;
        float sq = m4.x * m4.x + m4.y * m4.y + m4.z * m4.z + m4.w * m4.w;
#pragma unroll
        for (int off = 8; off; off >>= 1) {
            dr += __shfl_xor_sync(0xffffffffu, dr, off);
            dw += __shfl_xor_sync(0xffffffffu, dw, off);
            sq += __shfl_xor_sync(0xffffffffu, sq, off);
        }
        if (mg == 0) {
            float nm = sqrtf(sq) + 1e-8f;
            g_sim_r[ro] = dr / (nrm[0] * nm);
            g_sim_w[ro] = dw / (nrm[1] * nm);
        }
    }
}

// ------------------------- addressing (softmax/interp/shift/sharpen) --------
// grid 512 blocks: [0,256) = read head, [256,512) = write head.  block 256.

__global__ void addressing_kernel(const float* __restrict__ read_w_prev,
                                  const float* __restrict__ write_w_prev,
                                  float* __restrict__ w_read, float* __restrict__ w_write) {
    int b = blockIdx.x & 255;
    bool isw = blockIdx.x >= 256;
    const float* ov = g_rw + (size_t)b * NRW + (isw ? 70 : 0);
    const float* sim = (isw ? g_sim_w : g_sim_r) + (size_t)b * Nn;
    const float* prev = (isw ? write_w_prev : read_w_prev) + (size_t)b * Nn;
    float* wout = (isw ? w_write : w_read) + (size_t)b * Nn;

    __shared__ float wg[Nn];
    __shared__ float red[256];
    int t = threadIdx.x;

    float beta  = softplus(ov[64]);
    float g     = sigm(ov[65]);
    float s0 = ov[66], s1 = ov[67], s2 = ov[68];
    float smax = fmaxf(s0, fmaxf(s1, s2));
    float e0 = expf(s0 - smax), e1 = expf(s1 - smax), e2 = expf(s2 - smax);
    float es = e0 + e1 + e2;
    e0 /= es; e1 /= es; e2 /= es;
    float gamma = 1.f + softplus(ov[69]);

    // phase 1: softmax(beta*sim) -> interp with prev
    float loc[8];
    float mx = -1e30f;
#pragma unroll
    for (int i = 0; i < 8; i++) {
        float v = beta * sim[t + i * 256];
        loc[i] = v;
        mx = fmaxf(mx, v);
    }
    red[t] = mx; __syncthreads();
    for (int off = 128; off; off >>= 1) {
        if (t < off) red[t] = fmaxf(red[t], red[t + off]);
        __syncthreads();
    }
    mx = red[0]; __syncthreads();
    float sum = 0.f;
#pragma unroll
    for (int i = 0; i < 8; i++) { loc[i] = expf(loc[i] - mx); sum += loc[i]; }
    red[t] = sum; __syncthreads();
    for (int off = 128; off; off >>= 1) {
        if (t < off) red[t] += red[t + off];
        __syncthreads();
    }
    float inv = 1.f / red[0]; __syncthreads();
#pragma unroll
    for (int i = 0; i < 8; i++) {
        int n = t + i * 256;
        wg[n] = g * loc[i] * inv + (1.f - g) * prev[n];
    }
    __syncthreads();

    // phase 2: shift + sharpen + normalize
    float ws[8];
    float sum2 = 0.f;
#pragma unroll
    for (int i = 0; i < 8; i++) {
        int n = t + i * 256;
        float v = e0 * wg[(n + Nn - 1) & (Nn - 1)] + e1 * wg[n] + e2 * wg[(n + 1) & (Nn - 1)];
        v = powf(v, gamma);
        ws[i] = v;
        sum2 += v;
    }
    red[t] = sum2; __syncthreads();
    for (int off = 128; off; off >>= 1) {
        if (t < off) red[t] += red[t + off];
        __syncthreads();
    }
    float inv2 = 1.f / (red[0] + 1e-8f);
#pragma unroll
    for (int i = 0; i < 8; i++) wout[t + i * 256] = ws[i] * inv2;
}

// ------------------------- memory update + read_vec (1 read + 1 write) ------
// grid (Nn/128, Bb), block 256.

__global__ void update_kernel(const float* __restrict__ mem,
                              const float* __restrict__ w_read,
                              const float* __restrict__ w_write,
                              float* __restrict__ mem_out,
                              float* __restrict__ read_vec) {
    int b = blockIdx.y;
    int n0 = blockIdx.x * 128;
    __shared__ float er[64], ad[64];
    int t = threadIdx.x;
    const float* wo = g_rw + (size_t)b * NRW;
    if (t < 64) {
        er[t] = sigm(wo[140 + t]);  // 70 + (M+6)
        ad[t] = wo[204 + t];        // 70 + (2M+6)
    }
    __syncthreads();
    int mg = t & 15, rg = t >> 4;
    float4 e4 = *(const float4*)&er[mg * 4];
    float4 a4 = *(const float4*)&ad[mg * 4];
    float4 acc = make_float4(0.f, 0.f, 0.f, 0.f);
#pragma unroll
    for (int i = 0; i < 8; i++) {
        int n = n0 + i * 16 + rg;
        size_t ro = (size_t)b * Nn + n;
        float ww = w_write[ro];
        float wr = w_read[ro];
        float4 m4 = *(const float4*)(mem + ro * 64 + mg * 4);
        float4 o;
        o.x = m4.x * (1.f - ww * e4.x) + ww * a4.x;
        o.y = m4.y * (1.f - ww * e4.y) + ww * a4.y;
        o.z = m4.z * (1.f - ww * e4.z) + ww * a4.z;
        o.w = m4.w * (1.f - ww * e4.w) + ww * a4.w;
        *(float4*)(mem_out + ro * 64 + mg * 4) = o;
        acc.x += wr * m4.x; acc.y += wr * m4.y;
        acc.z += wr * m4.z; acc.w += wr * m4.w;
    }
    float* rv = read_vec + (size_t)b * Mm + mg * 4;
    atomicAdd(rv + 0, acc.x);
    atomicAdd(rv + 1, acc.y);
    atomicAdd(rv + 2, acc.z);
    atomicAdd(rv + 3, acc.w);
}

// ---------------------------------------------------------------------------

extern "C" void kernel_launch(void* const* d_in, const int* in_sizes, int n_in,
                              void* d_out, int out_size) {
    const float* x         = (const float*)d_in[0];
    const float* memory    = (const float*)d_in[1];
    const float* h         = (const float*)d_in[2];
    const float* c         = (const float*)d_in[3];
    const float* read_w    = (const float*)d_in[4];
    const float* write_w   = (const float*)d_in[5];
    const float* prev_read = (const float*)d_in[6];
    const float* W_ih      = (const float*)d_in[7];
    const float* W_hh      = (const float*)d_in[8];
    const float* b_ih      = (const float*)d_in[9];
    const float* b_hh      = (const float*)d_in[10];
    const float* W_r       = (const float*)d_in[11];
    const float* b_r       = (const float*)d_in[12];
    const float* W_w       = (const float*)d_in[13];
    const float* b_w       = (const float*)d_in[14];
    const float* W_o       = (const float*)d_in[15];
    const float* b_o       = (const float*)d_in[16];

    float* out  = (float*)d_out;
    float* o_out = out + OFF_OUT;
    float* o_mem = out + OFF_MEM;
    float* o_h   = out + OFF_H;
    float* o_c   = out + OFF_C;
    float* o_wr  = out + OFF_WR;
    float* o_ww  = out + OFF_WW;
    float* o_rv  = out + OFF_RV;

    float *A1, *Wg, *bg, *gates, *Wrw, *brw, *A2;
    cudaGetSymbolAddress((void**)&A1,    g_A1);
    cudaGetSymbolAddress((void**)&Wg,    g_Wg);
    cudaGetSymbolAddress((void**)&bg,    g_bg);
    cudaGetSymbolAddress((void**)&gates, g_gates);
    cudaGetSymbolAddress((void**)&Wrw,   g_Wrw);
    cudaGetSymbolAddress((void**)&brw,   g_brw);
    cudaGetSymbolAddress((void**)&A2,    g_A2);

    // 1. weight packing + read_vec zero (independent)
    prep_weights<<<(NG * KG + 255) / 256, 256>>>(W_ih, W_hh, b_ih, b_hh,
                                                 W_r, b_r, W_w, b_w, o_rv);
    // 2. concat input
    prep_A1<<<(Bb * KG + 255) / 256, 256>>>(x, prev_read, h);
    // 3. gates GEMM  [256,832] x [2048,832]^T
    sgemm_tn<<<dim3(NG / 64, Bb / 64), 256>>>(A1, Wg, bg, gates, Bb, NG, KG);
    // 4. LSTM pointwise -> h_new, c_new
    lstm_pw<<<(Bb * CS + 255) / 256, 256>>>(c, o_h, o_c);
    // 5. addressing GEMM  h_new x [268,512]^T
    float* rw_scratch;
    cudaGetSymbolAddress((void**)&rw_scratch, g_rw);
    sgemm_tn<<<dim3((NRW + 63) / 64, Bb / 64), 256>>>(o_h, Wrw, brw, rw_scratch,
                                                      Bb, NRW, CS);
    // 6. similarity pass (single read of memory)
    sim_kernel<<<dim3(Nn / 64, Bb), 256>>>(memory);
    // 7. addressing (read + write heads)
    addressing_kernel<<<512, 256>>>(read_w, write_w, o_wr, o_ww);
    // 8. memory update + read_vec
    update_kernel<<<dim3(Nn / 128, Bb), 256>>>(memory, o_wr, o_ww, o_mem, o_rv);
    // 9. concat [h_new | read_vec]
    prep_A2<<<(Bb * (CS + Mm) + 255) / 256, 256>>>(o_h, o_rv);
    // 10. output GEMM
    sgemm_tn<<<dim3(256 / 64, Bb / 64), 256>>>(A2, W_o, b_o, o_out, Bb, 256, CS + Mm);
}

// round 2
// speedup vs baseline: 1.4395x; 1.4395x over previous
#include <cuda_runtime.h>
#include <cstdint>
#include <cstddef>

// ---------------------------------------------------------------------------
// NTM single step.  B=256, N=2048, M=64, CS=512, INP=256, OUT=256
// ---------------------------------------------------------------------------

#define Bb 256
#define Nn 2048
#define Mm 64
#define CS 512
#define KG 832      // INP + M + CS
#define NG 2048     // 4*CS
#define NRW 268     // ADDR_R(70) + ADDR_W(198)

// output offsets (elements)
#define OFF_OUT 0
#define OFF_MEM 65536
#define OFF_H   33619968
#define OFF_C   33751040
#define OFF_WR  33882112
#define OFF_WW  34406400
#define OFF_RV  34930688

// scratch
__device__ float g_A1[Bb * KG];
__device__ float g_Wg[NG * KG];
__device__ float g_bg[NG];
__device__ float g_gates[Bb * NG];
__device__ float g_Wrw[NRW * CS];
__device__ float g_brw[NRW];
__device__ float g_rw[Bb * NRW];
__device__ float g_sim_r[Bb * Nn];
__device__ float g_sim_w[Bb * Nn];
__device__ float g_A2[Bb * (CS + Mm)];

__device__ __forceinline__ float sigm(float x) { return 1.f / (1.f + __expf(-x)); }
__device__ __forceinline__ float ftanh(float x) {
    float e = __expf(2.f * x);
    return (e - 1.f) / (e + 1.f);
}
__device__ __forceinline__ float softplus(float x) { return x > 20.f ? x : log1pf(expf(x)); }
__device__ __forceinline__ float to_tf32(float x) {
    float r; asm("cvt.rna.tf32.f32 %0, %1;" : "=f"(r) : "f"(x)); return r;
}

// ------------------------- combined prep ------------------------------------

__global__ void prep_all(const float* __restrict__ Wih, const float* __restrict__ Whh,
                         const float* __restrict__ bih, const float* __restrict__ bhh,
                         const float* __restrict__ Wr,  const float* __restrict__ br,
                         const float* __restrict__ Ww,  const float* __restrict__ bw,
                         const float* __restrict__ x,   const float* __restrict__ prev_read,
                         const float* __restrict__ h,   float* __restrict__ rv_zero) {
    int idx = blockIdx.x * blockDim.x + threadIdx.x;
    if (idx < NG * KG) {
        int n = idx / KG, k = idx - n * KG;
        g_Wg[idx] = (k < 320) ? Wih[n * 320 + k] : Whh[n * 512 + (k - 320)];
    }
    if (idx < NG) g_bg[idx] = bih[idx] + bhh[idx];
    if (idx < NRW * CS) {
        int r = idx / CS, k = idx - r * CS;
        g_Wrw[idx] = (r < 70) ? Wr[idx] : Ww[(r - 70) * CS + k];
    }
    if (idx < NRW) g_brw[idx] = (idx < 70) ? br[idx] : bw[idx - 70];
    if (idx < Bb * Mm) rv_zero[idx] = 0.f;
    if (idx < Bb * KG) {
        int b = idx / KG, k = idx - b * KG;
        float v;
        if (k < 256)      v = x[b * 256 + k];
        else if (k < 320) v = prev_read[b * 64 + (k - 256)];
        else              v = h[b * 512 + (k - 320)];
        g_A1[idx] = v;
    }
}

__global__ void prep_A2(const float* __restrict__ h_new, const float* __restrict__ read_vec) {
    int idx = blockIdx.x * blockDim.x + threadIdx.x;
    if (idx >= Bb * (CS + Mm)) return;
    int b = idx / (CS + Mm), k = idx - b * (CS + Mm);
    g_A2[idx] = (k < CS) ? h_new[b * CS + k] : read_vec[b * Mm + (k - CS)];
}

// ------------------------- tf32 tensor-core GEMM ----------------------------
// C[M,N] = A[M,K] @ W[N,K]^T + bias.   tile 64x64, 128 threads (4 warps),
// BK=16, mma.sync.m16n8k8 tf32.  Requires M%64==0, K%16==0, N even.

__device__ __forceinline__ void mma_tf32(float* c, const uint32_t* a,
                                         uint32_t b0, uint32_t b1) {
    asm volatile(
        "mma.sync.aligned.m16n8k8.row.col.f32.tf32.tf32.f32 "
        "{%0,%1,%2,%3}, {%4,%5,%6,%7}, {%8,%9}, {%0,%1,%2,%3};\n"
        : "+f"(c[0]), "+f"(c[1]), "+f"(c[2]), "+f"(c[3])
        : "r"(a[0]), "r"(a[1]), "r"(a[2]), "r"(a[3]), "r"(b0), "r"(b1));
}

__global__ void gemm_tf32(const float* __restrict__ A, const float* __restrict__ W,
                          const float* __restrict__ bias, float* __restrict__ C,
                          int M, int N, int K) {
    __shared__ float As[64][20];   // [m][k], pad 20 -> conflict-free frag loads
    __shared__ float Bs[64][20];   // [n][k]
    int bm = blockIdx.y * 64, bn = blockIdx.x * 64;
    int tid = threadIdx.x;
    int wid = tid >> 5, lane = tid & 31;
    int wm = (wid & 1) * 32, wn = (wid >> 1) * 32;
    int gid = lane >> 2, tig = lane & 3;

    float acc[2][4][4];
#pragma unroll
    for (int i = 0; i < 2; i++)
#pragma unroll
        for (int j = 0; j < 4; j++)
#pragma unroll
            for (int q = 0; q < 4; q++) acc[i][j][q] = 0.f;

    for (int k0 = 0; k0 < K; k0 += 16) {
#pragma unroll
        for (int i = 0; i < 2; i++) {
            int fi = tid + i * 128;           // 0..255
            int r = fi >> 2, cc = (fi & 3) << 2;
            float4 v = *(const float4*)(A + (size_t)(bm + r) * K + k0 + cc);
            As[r][cc + 0] = to_tf32(v.x); As[r][cc + 1] = to_tf32(v.y);
            As[r][cc + 2] = to_tf32(v.z); As[r][cc + 3] = to_tf32(v.w);
            int wr = bn + r;
            float4 wv = make_float4(0.f, 0.f, 0.f, 0.f);
            if (wr < N) wv = *(const float4*)(W + (size_t)wr * K + k0 + cc);
            Bs[r][cc + 0] = to_tf32(wv.x); Bs[r][cc + 1] = to_tf32(wv.y);
            Bs[r][cc + 2] = to_tf32(wv.z); Bs[r][cc + 3] = to_tf32(wv.w);
        }
        __syncthreads();
#pragma unroll
        for (int kk = 0; kk < 16; kk += 8) {
            uint32_t a[2][4];
#pragma unroll
            for (int i = 0; i < 2; i++) {
                int r0 = wm + i * 16 + gid;
                a[i][0] = __float_as_uint(As[r0][kk + tig]);
                a[i][1] = __float_as_uint(As[r0 + 8][kk + tig]);
                a[i][2] = __float_as_uint(As[r0][kk + tig + 4]);
                a[i][3] = __float_as_uint(As[r0 + 8][kk + tig + 4]);
            }
#pragma unroll
            for (int j = 0; j < 4; j++) {
                int c0 = wn + j * 8 + gid;
                uint32_t b0 = __float_as_uint(Bs[c0][kk + tig]);
                uint32_t b1 = __float_as_uint(Bs[c0][kk + tig + 4]);
#pragma unroll
                for (int i = 0; i < 2; i++) mma_tf32(acc[i][j], a[i], b0, b1);
            }
        }
        __syncthreads();
    }

#pragma unroll
    for (int i = 0; i < 2; i++) {
        int row = bm + wm + i * 16 + gid;
#pragma unroll
        for (int j = 0; j < 4; j++) {
            int col = bn + wn + j * 8 + tig * 2;
            if (col < N) {
                float b0 = bias[col], b1 = bias[col + 1];
                C[(size_t)row * N + col]           = acc[i][j][0] + b0;
                C[(size_t)row * N + col + 1]       = acc[i][j][1] + b1;
                C[(size_t)(row + 8) * N + col]     = acc[i][j][2] + b0;
                C[(size_t)(row + 8) * N + col + 1] = acc[i][j][3] + b1;
            }
        }
    }
}

// ------------------------- LSTM pointwise ----------------------------------

__global__ void lstm_pw(const float* __restrict__ c_in,
                        float* __restrict__ h_out, float* __restrict__ c_out) {
    int idx = blockIdx.x * blockDim.x + threadIdx.x;
    if (idx >= Bb * CS) return;
    int b = idx >> 9, j = idx & 511;
    const float* g = g_gates + (size_t)b * NG;
    float ig = sigm(g[j]);
    float fg = sigm(g[512 + j]);
    float gg = ftanh(g[1024 + j]);
    float og = sigm(g[1536 + j]);
    float cn = fg * c_in[idx] + ig * gg;
    float hn = og * ftanh(cn);
    c_out[idx] = cn;
    h_out[idx] = hn;
}

// ------------------------- similarity pass (1 read of memory) ---------------

__global__ void sim_kernel(const float* __restrict__ mem) {
    int b = blockIdx.y;
    int n0 = blockIdx.x * 64;
    __shared__ float kr[64], kw[64];
    __shared__ float nrm[2];
    int t = threadIdx.x;
    const float* base = g_rw + (size_t)b * NRW;
    if (t < 64)       kr[t] = base[t];
    else if (t < 128) kw[t - 64] = base[70 + (t - 64)];
    __syncthreads();
    if (t == 0) {
        float s = 0.f;
        for (int i = 0; i < 64; i++) s += kr[i] * kr[i];
        nrm[0] = sqrtf(s) + 1e-8f;
    } else if (t == 32) {
        float s = 0.f;
        for (int i = 0; i < 64; i++) s += kw[i] * kw[i];
        nrm[1] = sqrtf(s) + 1e-8f;
    }
    __syncthreads();
    int mg = t & 15, rg = t >> 4;
    float4 kr4 = *(const float4*)&kr[mg * 4];
    float4 kw4 = *(const float4*)&kw[mg * 4];
#pragma unroll
    for (int i = 0; i < 4; i++) {
        int n = n0 + i * 16 + rg;
        size_t ro = (size_t)b * Nn + n;
        float4 m4 = *(const float4*)(mem + ro * 64 + mg * 4);
        float dr = m4.x * kr4.x + m4.y * kr4.y + m4.z * kr4.z + m4.w * kr4.w;
        float dw = m4.x * kw4.x + m4.y * kw4.y + m4.z * kw4.z + m4.w * kw4.w;
        float sq = m4.x * m4.x + m4.y * m4.y + m4.z * m4.z + m4.w * m4.w;
#pragma unroll
        for (int off = 8; off; off >>= 1) {
            dr += __shfl_xor_sync(0xffffffffu, dr, off);
            dw += __shfl_xor_sync(0xffffffffu, dw, off);
            sq += __shfl_xor_sync(0xffffffffu, sq, off);
        }
        if (mg == 0) {
            float nm = sqrtf(sq) + 1e-8f;
            g_sim_r[ro] = dr / (nrm[0] * nm);
            g_sim_w[ro] = dw / (nrm[1] * nm);
        }
    }
}

// ------------------------- addressing ---------------------------------------
// grid 512 blocks: [0,256) = read head, [256,512) = write head.  block 256.

__global__ void addressing_kernel(const float* __restrict__ read_w_prev,
                                  const float* __restrict__ write_w_prev,
                                  float* __restrict__ w_read, float* __restrict__ w_write) {
    int b = blockIdx.x & 255;
    bool isw = blockIdx.x >= 256;
    const float* ov = g_rw + (size_t)b * NRW + (isw ? 70 : 0);
    const float* sim = (isw ? g_sim_w : g_sim_r) + (size_t)b * Nn;
    const float* prev = (isw ? write_w_prev : read_w_prev) + (size_t)b * Nn;
    float* wout = (isw ? w_write : w_read) + (size_t)b * Nn;

    __shared__ float wg[Nn];
    __shared__ float red[256];
    int t = threadIdx.x;

    float beta  = softplus(ov[64]);
    float g     = sigm(ov[65]);
    float s0 = ov[66], s1 = ov[67], s2 = ov[68];
    float smax = fmaxf(s0, fmaxf(s1, s2));
    float e0 = __expf(s0 - smax), e1 = __expf(s1 - smax), e2 = __expf(s2 - smax);
    float es = e0 + e1 + e2;
    e0 /= es; e1 /= es; e2 /= es;
    float gamma = 1.f + softplus(ov[69]);

    float loc[8];
    float mx = -1e30f;
#pragma unroll
    for (int i = 0; i < 8; i++) {
        float v = beta * sim[t + i * 256];
        loc[i] = v;
        mx = fmaxf(mx, v);
    }
    red[t] = mx; __syncthreads();
    for (int off = 128; off; off >>= 1) {
        if (t < off) red[t] = fmaxf(red[t], red[t + off]);
        __syncthreads();
    }
    mx = red[0]; __syncthreads();
    float sum = 0.f;
#pragma unroll
    for (int i = 0; i < 8; i++) { loc[i] = __expf(loc[i] - mx); sum += loc[i]; }
    red[t] = sum; __syncthreads();
    for (int off = 128; off; off >>= 1) {
        if (t < off) red[t] += red[t + off];
        __syncthreads();
    }
    float inv = 1.f / red[0]; __syncthreads();
#pragma unroll
    for (int i = 0; i < 8; i++) {
        int n = t + i * 256;
        wg[n] = g * loc[i] * inv + (1.f - g) * prev[n];
    }
    __syncthreads();

    float ws[8];
    float sum2 = 0.f;
#pragma unroll
    for (int i = 0; i < 8; i++) {
        int n = t + i * 256;
        float v = e0 * wg[(n + Nn - 1) & (Nn - 1)] + e1 * wg[n] + e2 * wg[(n + 1) & (Nn - 1)];
        v = __powf(v, gamma);
        ws[i] = v;
        sum2 += v;
    }
    red[t] = sum2; __syncthreads();
    for (int off = 128; off; off >>= 1) {
        if (t < off) red[t] += red[t + off];
        __syncthreads();
    }
    float inv2 = 1.f / (red[0] + 1e-8f);
#pragma unroll
    for (int i = 0; i < 8; i++) wout[t + i * 256] = ws[i] * inv2;
}

// ------------------------- memory update + read_vec -------------------------

__global__ void update_kernel(const float* __restrict__ mem,
                              const float* __restrict__ w_read,
                              const float* __restrict__ w_write,
                              float* __restrict__ mem_out,
                              float* __restrict__ read_vec) {
    int b = blockIdx.y;
    int n0 = blockIdx.x * 128;
    __shared__ float er[64], ad[64];
    int t = threadIdx.x;
    const float* wo = g_rw + (size_t)b * NRW;
    if (t < 64) {
        er[t] = sigm(wo[140 + t]);  // 70 + (M+6)
        ad[t] = wo[204 + t];        // 70 + (2M+6)
    }
    __syncthreads();
    int mg = t & 15, rg = t >> 4;
    float4 e4 = *(const float4*)&er[mg * 4];
    float4 a4 = *(const float4*)&ad[mg * 4];
    float4 acc = make_float4(0.f, 0.f, 0.f, 0.f);
#pragma unroll
    for (int i = 0; i < 8; i++) {
        int n = n0 + i * 16 + rg;
        size_t ro = (size_t)b * Nn + n;
        float ww = w_write[ro];
        float wr = w_read[ro];
        float4 m4 = *(const float4*)(mem + ro * 64 + mg * 4);
        float4 o;
        o.x = m4.x * (1.f - ww * e4.x) + ww * a4.x;
        o.y = m4.y * (1.f - ww * e4.y) + ww * a4.y;
        o.z = m4.z * (1.f - ww * e4.z) + ww * a4.z;
        o.w = m4.w * (1.f - ww * e4.w) + ww * a4.w;
        *(float4*)(mem_out + ro * 64 + mg * 4) = o;
        acc.x += wr * m4.x; acc.y += wr * m4.y;
        acc.z += wr * m4.z; acc.w += wr * m4.w;
    }
    float* rv = read_vec + (size_t)b * Mm + mg * 4;
    atomicAdd(rv + 0, acc.x);
    atomicAdd(rv + 1, acc.y);
    atomicAdd(rv + 2, acc.z);
    atomicAdd(rv + 3, acc.w);
}

// ---------------------------------------------------------------------------

extern "C" void kernel_launch(void* const* d_in, const int* in_sizes, int n_in,
                              void* d_out, int out_size) {
    const float* x         = (const float*)d_in[0];
    const float* memory    = (const float*)d_in[1];
    const float* h         = (const float*)d_in[2];
    const float* c         = (const float*)d_in[3];
    const float* read_w    = (const float*)d_in[4];
    const float* write_w   = (const float*)d_in[5];
    const float* prev_read = (const float*)d_in[6];
    const float* W_ih      = (const float*)d_in[7];
    const float* W_hh      = (const float*)d_in[8];
    const float* b_ih      = (const float*)d_in[9];
    const float* b_hh      = (const float*)d_in[10];
    const float* W_r       = (const float*)d_in[11];
    const float* b_r       = (const float*)d_in[12];
    const float* W_w       = (const float*)d_in[13];
    const float* b_w       = (const float*)d_in[14];
    const float* W_o       = (const float*)d_in[15];
    const float* b_o       = (const float*)d_in[16];

    float* out  = (float*)d_out;
    float* o_out = out + OFF_OUT;
    float* o_mem = out + OFF_MEM;
    float* o_h   = out + OFF_H;
    float* o_c   = out + OFF_C;
    float* o_wr  = out + OFF_WR;
    float* o_ww  = out + OFF_WW;
    float* o_rv  = out + OFF_RV;

    float *A1, *Wg, *bg, *gates, *Wrw, *brw, *A2, *rw;
    cudaGetSymbolAddress((void**)&A1,    g_A1);
    cudaGetSymbolAddress((void**)&Wg,    g_Wg);
    cudaGetSymbolAddress((void**)&bg,    g_bg);
    cudaGetSymbolAddress((void**)&gates, g_gates);
    cudaGetSymbolAddress((void**)&Wrw,   g_Wrw);
    cudaGetSymbolAddress((void**)&brw,   g_brw);
    cudaGetSymbolAddress((void**)&A2,    g_A2);
    cudaGetSymbolAddress((void**)&rw,    g_rw);

    // 1. weight packing + input concat + rv zero
    prep_all<<<(NG * KG + 255) / 256, 256>>>(W_ih, W_hh, b_ih, b_hh, W_r, b_r,
                                             W_w, b_w, x, prev_read, h, o_rv);
    // 2. gates GEMM  [256,832] x [2048,832]^T  (tf32 MMA)
    gemm_tf32<<<dim3(NG / 64, Bb / 64), 128>>>(A1, Wg, bg, gates, Bb, NG, KG);
    // 3. LSTM pointwise -> h_new, c_new
    lstm_pw<<<(Bb * CS + 255) / 256, 256>>>(c, o_h, o_c);
    // 4. addressing GEMM  h_new x [268,512]^T
    gemm_tf32<<<dim3((NRW + 63) / 64, Bb / 64), 128>>>(o_h, Wrw, brw, rw, Bb, NRW, CS);
    // 5. similarity pass (single read of memory)
    sim_kernel<<<dim3(Nn / 64, Bb), 256>>>(memory);
    // 6. addressing (read + write heads)
    addressing_kernel<<<512, 256>>>(read_w, write_w, o_wr, o_ww);
    // 7. memory update + read_vec
    update_kernel<<<dim3(Nn / 128, Bb), 256>>>(memory, o_wr, o_ww, o_mem, o_rv);
    // 8. concat [h_new | read_vec]
    prep_A2<<<(Bb * (CS + Mm) + 255) / 256, 256>>>(o_h, o_rv);
    // 9. output GEMM
    gemm_tf32<<<dim3(256 / 64, Bb / 64), 128>>>(A2, W_o, b_o, o_out, Bb, 256, CS + Mm);
}

// round 3
// speedup vs baseline: 1.7068x; 1.1857x over previous
#include <cuda_runtime.h>
#include <cstdint>
#include <cstddef>

// ---------------------------------------------------------------------------
// NTM single step.  B=256, N=2048, M=64, CS=512, INP=256, OUT=256
// ---------------------------------------------------------------------------

#define Bb 256
#define Nn 2048
#define Mm 64
#define CS 512
#define KG 832      // INP + M + CS
#define NG 2048     // 4*CS
#define NRW 268     // ADDR_R(70) + ADDR_W(198)

// output offsets (elements)
#define OFF_OUT 0
#define OFF_MEM 65536
#define OFF_H   33619968
#define OFF_C   33751040
#define OFF_WR  33882112
#define OFF_WW  34406400
#define OFF_RV  34930688

// scratch
__device__ float g_A1[Bb * KG];
__device__ float g_Wg[NG * KG];
__device__ float g_bg[NG];
__device__ float g_gates[Bb * NG];
__device__ float g_Wrw[NRW * CS];
__device__ float g_brw[NRW];
__device__ float g_rw[Bb * NRW];
__device__ float g_sim_r[Bb * Nn];
__device__ float g_sim_w[Bb * Nn];
__device__ float g_A2[Bb * (CS + Mm)];

__device__ __forceinline__ float sigm(float x) { return 1.f / (1.f + __expf(-x)); }
__device__ __forceinline__ float ftanh(float x) {
    float e = __expf(2.f * x);
    return (e - 1.f) / (e + 1.f);
}
__device__ __forceinline__ float softplus(float x) { return x > 20.f ? x : log1pf(expf(x)); }
__device__ __forceinline__ float to_tf32(float x) {
    float r; asm("cvt.rna.tf32.f32 %0, %1;" : "=f"(r) : "f"(x)); return r;
}

// ------------------------- combined prep (float4) ---------------------------

__global__ void prep_all(const float4* __restrict__ Wih, const float4* __restrict__ Whh,
                         const float4* __restrict__ bih, const float4* __restrict__ bhh,
                         const float4* __restrict__ Wr,  const float* __restrict__ br,
                         const float4* __restrict__ Ww,  const float* __restrict__ bw,
                         const float4* __restrict__ x,   const float4* __restrict__ prev_read,
                         const float4* __restrict__ h,   float4* __restrict__ rv_zero) {
    int idx = blockIdx.x * blockDim.x + threadIdx.x;
    // Wg pack: NG rows x 208 float4 (80 from Wih, 128 from Whh)
    if (idx < NG * 208) {
        int n = idx / 208, f = idx - n * 208;
        ((float4*)g_Wg)[idx] = (f < 80) ? Wih[n * 80 + f] : Whh[n * 128 + (f - 80)];
    }
    if (idx < NG / 4) {
        float4 a = bih[idx], b = bhh[idx];
        ((float4*)g_bg)[idx] = make_float4(a.x + b.x, a.y + b.y, a.z + b.z, a.w + b.w);
    }
    // Wrw pack: 268 rows x 128 float4
    if (idx < NRW * 128) {
        int r = idx >> 7, f = idx & 127;
        ((float4*)g_Wrw)[idx] = (r < 70) ? Wr[idx] : Ww[(r - 70) * 128 + f];
    }
    if (idx < NRW) g_brw[idx] = (idx < 70) ? br[idx] : bw[idx - 70];
    if (idx < Bb * Mm / 4) rv_zero[idx] = make_float4(0.f, 0.f, 0.f, 0.f);
    // A1 concat: Bb rows x 208 float4 (64 x | 16 prev_read | 128 h)
    if (idx < Bb * 208) {
        int b = idx / 208, f = idx - b * 208;
        float4 v;
        if (f < 64)      v = x[b * 64 + f];
        else if (f < 80) v = prev_read[b * 16 + (f - 64)];
        else             v = h[b * 128 + (f - 80)];
        ((float4*)g_A1)[idx] = v;
    }
}

__global__ void prep_A2(const float4* __restrict__ h_new, const float4* __restrict__ read_vec) {
    int idx = blockIdx.x * blockDim.x + threadIdx.x;
    if (idx >= Bb * 144) return;   // 576/4
    int b = idx / 144, f = idx - b * 144;
    ((float4*)g_A2)[idx] = (f < 128) ? h_new[b * 128 + f] : read_vec[b * 16 + (f - 128)];
}

// ------------------------- tf32 tensor-core GEMM (pipelined) ----------------
// C[M,N] = A[M,K] @ W[N,K]^T + bias.  tile 64x64, 256 threads (8 warps,
// 2x4 warp grid, 32x16 per warp), BK=16, double-buffered smem, global
// prefetch into registers.  Requires M%64==0, K%16==0, N even.

__device__ __forceinline__ void mma_tf32(float* c, const uint32_t* a,
                                         uint32_t b0, uint32_t b1) {
    asm volatile(
        "mma.sync.aligned.m16n8k8.row.col.f32.tf32.tf32.f32 "
        "{%0,%1,%2,%3}, {%4,%5,%6,%7}, {%8,%9}, {%0,%1,%2,%3};\n"
        : "+f"(c[0]), "+f"(c[1]), "+f"(c[2]), "+f"(c[3])
        : "r"(a[0]), "r"(a[1]), "r"(a[2]), "r"(a[3]), "r"(b0), "r"(b1));
}

__global__ void __launch_bounds__(256, 2)
gemm_tf32(const float* __restrict__ A, const float* __restrict__ W,
          const float* __restrict__ bias, float* __restrict__ C,
          int M, int N, int K) {
    __shared__ float As[2][64][20];
    __shared__ float Bs[2][64][20];
    int bm = blockIdx.y * 64, bn = blockIdx.x * 64;
    int tid = threadIdx.x;
    int wid = tid >> 5, lane = tid & 31;
    int wm = (wid & 1) * 32, wn = (wid >> 1) * 16;
    int gid = lane >> 2, tig = lane & 3;

    // global load mapping: thread -> (row r, 4 consecutive k at c4)
    int r = tid >> 2;            // 0..63
    int c4 = (tid & 3) << 2;     // 0,4,8,12
    const float* Ap = A + (size_t)(bm + r) * K + c4;
    bool wvalid = (bn + r) < N;
    const float* Wp = W + (size_t)(wvalid ? (bn + r) : 0) * K + c4;

    float acc[2][2][4];
#pragma unroll
    for (int i = 0; i < 2; i++)
#pragma unroll
        for (int j = 0; j < 2; j++)
#pragma unroll
            for (int q = 0; q < 4; q++) acc[i][j][q] = 0.f;

    const float4 z4 = make_float4(0.f, 0.f, 0.f, 0.f);
    // preload tile 0
    float4 av = *(const float4*)Ap;
    float4 wv = wvalid ? *(const float4*)Wp : z4;
    As[0][r][c4 + 0] = to_tf32(av.x); As[0][r][c4 + 1] = to_tf32(av.y);
    As[0][r][c4 + 2] = to_tf32(av.z); As[0][r][c4 + 3] = to_tf32(av.w);
    Bs[0][r][c4 + 0] = to_tf32(wv.x); Bs[0][r][c4 + 1] = to_tf32(wv.y);
    Bs[0][r][c4 + 2] = to_tf32(wv.z); Bs[0][r][c4 + 3] = to_tf32(wv.w);
    __syncthreads();

    int numK = K >> 4;
    for (int kt = 0; kt < numK; kt++) {
        int cur = kt & 1;
        float4 na, nw;
        bool more = (kt + 1) < numK;
        if (more) {
            na = *(const float4*)(Ap + (kt + 1) * 16);
            nw = wvalid ? *(const float4*)(Wp + (kt + 1) * 16) : z4;
        }
#pragma unroll
        for (int kk = 0; kk < 16; kk += 8) {
            uint32_t af[2][4];
#pragma unroll
            for (int i = 0; i < 2; i++) {
                int r0 = wm + i * 16 + gid;
                af[i][0] = __float_as_uint(As[cur][r0][kk + tig]);
                af[i][1] = __float_as_uint(As[cur][r0 + 8][kk + tig]);
                af[i][2] = __float_as_uint(As[cur][r0][kk + tig + 4]);
                af[i][3] = __float_as_uint(As[cur][r0 + 8][kk + tig + 4]);
            }
#pragma unroll
            for (int j = 0; j < 2; j++) {
                int c0 = wn + j * 8 + gid;
                uint32_t b0 = __float_as_uint(Bs[cur][c0][kk + tig]);
                uint32_t b1 = __float_as_uint(Bs[cur][c0][kk + tig + 4]);
#pragma unroll
                for (int i = 0; i < 2; i++) mma_tf32(acc[i][j], af[i], b0, b1);
            }
        }
        if (more) {
            int nxt = cur ^ 1;
            As[nxt][r][c4 + 0] = to_tf32(na.x); As[nxt][r][c4 + 1] = to_tf32(na.y);
            As[nxt][r][c4 + 2] = to_tf32(na.z); As[nxt][r][c4 + 3] = to_tf32(na.w);
            Bs[nxt][r][c4 + 0] = to_tf32(nw.x); Bs[nxt][r][c4 + 1] = to_tf32(nw.y);
            Bs[nxt][r][c4 + 2] = to_tf32(nw.z); Bs[nxt][r][c4 + 3] = to_tf32(nw.w);
            __syncthreads();
        }
    }

#pragma unroll
    for (int i = 0; i < 2; i++) {
        int row = bm + wm + i * 16 + gid;
#pragma unroll
        for (int j = 0; j < 2; j++) {
            int col = bn + wn + j * 8 + tig * 2;
            if (col < N) {
                float b0 = bias[col], b1 = bias[col + 1];
                C[(size_t)row * N + col]           = acc[i][j][0] + b0;
                C[(size_t)row * N + col + 1]       = acc[i][j][1] + b1;
                C[(size_t)(row + 8) * N + col]     = acc[i][j][2] + b0;
                C[(size_t)(row + 8) * N + col + 1] = acc[i][j][3] + b1;
            }
        }
    }
}

// ------------------------- LSTM pointwise (float4) ---------------------------

__global__ void lstm_pw(const float4* __restrict__ c_in,
                        float4* __restrict__ h_out, float4* __restrict__ c_out) {
    int idx = blockIdx.x * blockDim.x + threadIdx.x;
    if (idx >= Bb * CS / 4) return;
    int b = idx >> 7, q = idx & 127;
    const float* g = g_gates + (size_t)b * NG + q * 4;
    float4 i4 = *(const float4*)(g);
    float4 f4 = *(const float4*)(g + 512);
    float4 g4 = *(const float4*)(g + 1024);
    float4 o4 = *(const float4*)(g + 1536);
    float4 cv = c_in[idx];
    float4 cn, hn;
    cn.x = sigm(f4.x) * cv.x + sigm(i4.x) * ftanh(g4.x);
    cn.y = sigm(f4.y) * cv.y + sigm(i4.y) * ftanh(g4.y);
    cn.z = sigm(f4.z) * cv.z + sigm(i4.z) * ftanh(g4.z);
    cn.w = sigm(f4.w) * cv.w + sigm(i4.w) * ftanh(g4.w);
    hn.x = sigm(o4.x) * ftanh(cn.x);
    hn.y = sigm(o4.y) * ftanh(cn.y);
    hn.z = sigm(o4.z) * ftanh(cn.z);
    hn.w = sigm(o4.w) * ftanh(cn.w);
    c_out[idx] = cn;
    h_out[idx] = hn;
}

// ------------------------- similarity pass (1 read of memory) ---------------

__global__ void sim_kernel(const float* __restrict__ mem) {
    int b = blockIdx.y;
    int n0 = blockIdx.x * 64;
    __shared__ float kr[64], kw[64];
    __shared__ float nrm[2];
    int t = threadIdx.x;
    const float* base = g_rw + (size_t)b * NRW;
    if (t < 64)       kr[t] = base[t];
    else if (t < 128) kw[t - 64] = base[70 + (t - 64)];
    __syncthreads();
    if (t == 0) {
        float s = 0.f;
        for (int i = 0; i < 64; i++) s += kr[i] * kr[i];
        nrm[0] = sqrtf(s) + 1e-8f;
    } else if (t == 32) {
        float s = 0.f;
        for (int i = 0; i < 64; i++) s += kw[i] * kw[i];
        nrm[1] = sqrtf(s) + 1e-8f;
    }
    __syncthreads();
    int mg = t & 15, rg = t >> 4;
    float4 kr4 = *(const float4*)&kr[mg * 4];
    float4 kw4 = *(const float4*)&kw[mg * 4];
#pragma unroll
    for (int i = 0; i < 4; i++) {
        int n = n0 + i * 16 + rg;
        size_t ro = (size_t)b * Nn + n;
        float4 m4 = *(const float4*)(mem + ro * 64 + mg * 4);
        float dr = m4.x * kr4.x + m4.y * kr4.y + m4.z * kr4.z + m4.w * kr4.w;
        float dw = m4.x * kw4.x + m4.y * kw4.y + m4.z * kw4.z + m4.w * kw4.w;
        float sq = m4.x * m4.x + m4.y * m4.y + m4.z * m4.z + m4.w * m4.w;
#pragma unroll
        for (int off = 8; off; off >>= 1) {
            dr += __shfl_xor_sync(0xffffffffu, dr, off);
            dw += __shfl_xor_sync(0xffffffffu, dw, off);
            sq += __shfl_xor_sync(0xffffffffu, sq, off);
        }
        if (mg == 0) {
            float nm = sqrtf(sq) + 1e-8f;
            g_sim_r[ro] = dr / (nrm[0] * nm);
            g_sim_w[ro] = dw / (nrm[1] * nm);
        }
    }
}

// ------------------------- addressing ---------------------------------------

__global__ void addressing_kernel(const float* __restrict__ read_w_prev,
                                  const float* __restrict__ write_w_prev,
                                  float* __restrict__ w_read, float* __restrict__ w_write) {
    int b = blockIdx.x & 255;
    bool isw = blockIdx.x >= 256;
    const float* ov = g_rw + (size_t)b * NRW + (isw ? 70 : 0);
    const float* sim = (isw ? g_sim_w : g_sim_r) + (size_t)b * Nn;
    const float* prev = (isw ? write_w_prev : read_w_prev) + (size_t)b * Nn;
    float* wout = (isw ? w_write : w_read) + (size_t)b * Nn;

    __shared__ float wg[Nn];
    __shared__ float red[256];
    int t = threadIdx.x;

    float beta  = softplus(ov[64]);
    float g     = sigm(ov[65]);
    float s0 = ov[66], s1 = ov[67], s2 = ov[68];
    float smax = fmaxf(s0, fmaxf(s1, s2));
    float e0 = __expf(s0 - smax), e1 = __expf(s1 - smax), e2 = __expf(s2 - smax);
    float es = e0 + e1 + e2;
    e0 /= es; e1 /= es; e2 /= es;
    float gamma = 1.f + softplus(ov[69]);

    float loc[8];
    float mx = -1e30f;
#pragma unroll
    for (int i = 0; i < 8; i++) {
        float v = beta * sim[t + i * 256];
        loc[i] = v;
        mx = fmaxf(mx, v);
    }
    red[t] = mx; __syncthreads();
    for (int off = 128; off; off >>= 1) {
        if (t < off) red[t] = fmaxf(red[t], red[t + off]);
        __syncthreads();
    }
    mx = red[0]; __syncthreads();
    float sum = 0.f;
#pragma unroll
    for (int i = 0; i < 8; i++) { loc[i] = __expf(loc[i] - mx); sum += loc[i]; }
    red[t] = sum; __syncthreads();
    for (int off = 128; off; off >>= 1) {
        if (t < off) red[t] += red[t + off];
        __syncthreads();
    }
    float inv = 1.f / red[0]; __syncthreads();
#pragma unroll
    for (int i = 0; i < 8; i++) {
        int n = t + i * 256;
        wg[n] = g * loc[i] * inv + (1.f - g) * prev[n];
    }
    __syncthreads();

    float ws[8];
    float sum2 = 0.f;
#pragma unroll
    for (int i = 0; i < 8; i++) {
        int n = t + i * 256;
        float v = e0 * wg[(n + Nn - 1) & (Nn - 1)] + e1 * wg[n] + e2 * wg[(n + 1) & (Nn - 1)];
        v = __powf(v, gamma);
        ws[i] = v;
        sum2 += v;
    }
    red[t] = sum2; __syncthreads();
    for (int off = 128; off; off >>= 1) {
        if (t < off) red[t] += red[t + off];
        __syncthreads();
    }
    float inv2 = 1.f / (red[0] + 1e-8f);
#pragma unroll
    for (int i = 0; i < 8; i++) wout[t + i * 256] = ws[i] * inv2;
}

// ------------------------- memory update + read_vec -------------------------
// Reversed block order: sim_kernel just streamed memory through L2 (126MB);
// reading back-to-front maximizes L2 hits on the recently-touched tail.

__global__ void update_kernel(const float* __restrict__ mem,
                              const float* __restrict__ w_read,
                              const float* __restrict__ w_write,
                              float* __restrict__ mem_out,
                              float* __restrict__ read_vec) {
    int nblk = gridDim.x - 1 - blockIdx.x;
    int b    = gridDim.y - 1 - blockIdx.y;
    int n0 = nblk * 128;
    __shared__ float er[64], ad[64];
    int t = threadIdx.x;
    const float* wo = g_rw + (size_t)b * NRW;
    if (t < 64) {
        er[t] = sigm(wo[140 + t]);  // 70 + (M+6)
        ad[t] = wo[204 + t];        // 70 + (2M+6)
    }
    __syncthreads();
    int mg = t & 15, rg = t >> 4;
    float4 e4 = *(const float4*)&er[mg * 4];
    float4 a4 = *(const float4*)&ad[mg * 4];
    float4 acc = make_float4(0.f, 0.f, 0.f, 0.f);
#pragma unroll
    for (int i = 0; i < 8; i++) {
        int n = n0 + i * 16 + rg;
        size_t ro = (size_t)b * Nn + n;
        float ww = w_write[ro];
        float wr = w_read[ro];
        float4 m4 = *(const float4*)(mem + ro * 64 + mg * 4);
        float4 o;
        o.x = m4.x * (1.f - ww * e4.x) + ww * a4.x;
        o.y = m4.y * (1.f - ww * e4.y) + ww * a4.y;
        o.z = m4.z * (1.f - ww * e4.z) + ww * a4.z;
        o.w = m4.w * (1.f - ww * e4.w) + ww * a4.w;
        *(float4*)(mem_out + ro * 64 + mg * 4) = o;
        acc.x += wr * m4.x; acc.y += wr * m4.y;
        acc.z += wr * m4.z; acc.w += wr * m4.w;
    }
    float* rv = read_vec + (size_t)b * Mm + mg * 4;
    atomicAdd(rv + 0, acc.x);
    atomicAdd(rv + 1, acc.y);
    atomicAdd(rv + 2, acc.z);
    atomicAdd(rv + 3, acc.w);
}

// ---------------------------------------------------------------------------

extern "C" void kernel_launch(void* const* d_in, const int* in_sizes, int n_in,
                              void* d_out, int out_size) {
    const float* x         = (const float*)d_in[0];
    const float* memory    = (const float*)d_in[1];
    const float* h         = (const float*)d_in[2];
    const float* c         = (const float*)d_in[3];
    const float* read_w    = (const float*)d_in[4];
    const float* write_w   = (const float*)d_in[5];
    const float* prev_read = (const float*)d_in[6];
    const float* W_ih      = (const float*)d_in[7];
    const float* W_hh      = (const float*)d_in[8];
    const float* b_ih      = (const float*)d_in[9];
    const float* b_hh      = (const float*)d_in[10];
    const float* W_r       = (const float*)d_in[11];
    const float* b_r       = (const float*)d_in[12];
    const float* W_w       = (const float*)d_in[13];
    const float* b_w       = (const float*)d_in[14];
    const float* W_o       = (const float*)d_in[15];
    const float* b_o       = (const float*)d_in[16];

    float* out  = (float*)d_out;
    float* o_out = out + OFF_OUT;
    float* o_mem = out + OFF_MEM;
    float* o_h   = out + OFF_H;
    float* o_c   = out + OFF_C;
    float* o_wr  = out + OFF_WR;
    float* o_ww  = out + OFF_WW;
    float* o_rv  = out + OFF_RV;

    float *A1, *Wg, *bg, *gates, *Wrw, *brw, *A2, *rw;
    cudaGetSymbolAddress((void**)&A1,    g_A1);
    cudaGetSymbolAddress((void**)&Wg,    g_Wg);
    cudaGetSymbolAddress((void**)&bg,    g_bg);
    cudaGetSymbolAddress((void**)&gates, g_gates);
    cudaGetSymbolAddress((void**)&Wrw,   g_Wrw);
    cudaGetSymbolAddress((void**)&brw,   g_brw);
    cudaGetSymbolAddress((void**)&A2,    g_A2);
    cudaGetSymbolAddress((void**)&rw,    g_rw);

    // 1. weight packing + input concat + rv zero (float4 paths)
    prep_all<<<(NG * 208 + 255) / 256, 256>>>(
        (const float4*)W_ih, (const float4*)W_hh, (const float4*)b_ih,
        (const float4*)b_hh, (const float4*)W_r, b_r, (const float4*)W_w, b_w,
        (const float4*)x, (const float4*)prev_read, (const float4*)h,
        (float4*)o_rv);
    // 2. gates GEMM  [256,832] x [2048,832]^T  (tf32 MMA, pipelined)
    gemm_tf32<<<dim3(NG / 64, Bb / 64), 256>>>(A1, Wg, bg, gates, Bb, NG, KG);
    // 3. LSTM pointwise -> h_new, c_new
    lstm_pw<<<(Bb * CS / 4 + 255) / 256, 256>>>((const float4*)c,
                                                (float4*)o_h, (float4*)o_c);
    // 4. addressing GEMM  h_new x [268,512]^T
    gemm_tf32<<<dim3((NRW + 63) / 64, Bb / 64), 256>>>(o_h, Wrw, brw, rw, Bb, NRW, CS);
    // 5. similarity pass (single read of memory)
    sim_kernel<<<dim3(Nn / 64, Bb), 256>>>(memory);
    // 6. addressing (read + write heads)
    addressing_kernel<<<512, 256>>>(read_w, write_w, o_wr, o_ww);
    // 7. memory update + read_vec (reverse order for L2 reuse)
    update_kernel<<<dim3(Nn / 128, Bb), 256>>>(memory, o_wr, o_ww, o_mem, o_rv);
    // 8. concat [h_new | read_vec]
    prep_A2<<<(Bb * 144 + 255) / 256, 256>>>((const float4*)o_h, (const float4*)o_rv);
    // 9. output GEMM
    gemm_tf32<<<dim3(256 / 64, Bb / 64), 256>>>(A2, W_o, b_o, o_out, Bb, 256, CS + Mm);
}

// round 5
// speedup vs baseline: 2.0441x; 1.1977x over previous
#include <cuda_runtime.h>
#include <cstdint>
#include <cstddef>

// ---------------------------------------------------------------------------
// NTM single step.  B=256, N=2048, M=64, CS=512, INP=256, OUT=256
// ---------------------------------------------------------------------------

#define Bb 256
#define Nn 2048
#define Mm 64
#define CS 512
#define KG 832      // INP + M + CS
#define NG 2048     // 4*CS
#define NRW 268     // ADDR_R(70) + ADDR_W(198)
#define KO 576      // CS + M

// output offsets (elements)
#define OFF_OUT 0
#define OFF_MEM 65536
#define OFF_H   33619968
#define OFF_C   33751040
#define OFF_WR  33882112
#define OFF_WW  34406400
#define OFF_RV  34930688

// scratch (all GEMM operands pre-rounded to tf32 by producers)
__device__ float g_A1[Bb * KG];
__device__ float g_Wg[NG * KG];
__device__ float g_bg[NG];
__device__ float g_gates[Bb * NG];
__device__ float g_Wrw[NRW * CS];
__device__ float g_brw[NRW];
__device__ float g_rw[Bb * NRW];
__device__ float g_sim_r[Bb * Nn];
__device__ float g_sim_w[Bb * Nn];
__device__ float g_A2[Bb * KO];
__device__ float g_Wo[256 * KO];
__device__ float g_h32[Bb * CS];

__device__ __forceinline__ float sigm(float x) { return 1.f / (1.f + __expf(-x)); }
__device__ __forceinline__ float ftanh(float x) {
    float e = __expf(2.f * x);
    return (e - 1.f) / (e + 1.f);
}
__device__ __forceinline__ float softplus(float x) { return x > 20.f ? x : log1pf(expf(x)); }
__device__ __forceinline__ float to_tf32(float x) {
    float r; asm("cvt.rna.tf32.f32 %0, %1;" : "=f"(r) : "f"(x)); return r;
}
__device__ __forceinline__ float4 r4(float4 v) {
    return make_float4(to_tf32(v.x), to_tf32(v.y), to_tf32(v.z), to_tf32(v.w));
}

// ------------------------- combined prep (float4, tf32-rounded) --------------

__global__ void prep_all(const float4* __restrict__ Wih, const float4* __restrict__ Whh,
                         const float4* __restrict__ bih, const float4* __restrict__ bhh,
                         const float4* __restrict__ Wr,  const float* __restrict__ br,
                         const float4* __restrict__ Ww,  const float* __restrict__ bw,
                         const float4* __restrict__ x,   const float4* __restrict__ prev_read,
                         const float4* __restrict__ h,   const float4* __restrict__ Wo,
                         float4* __restrict__ rv_zero) {
    int idx = blockIdx.x * blockDim.x + threadIdx.x;
    // Wg pack: NG rows x 208 float4 (80 from Wih, 128 from Whh)
    if (idx < NG * 208) {
        int n = idx / 208, f = idx - n * 208;
        ((float4*)g_Wg)[idx] = r4((f < 80) ? Wih[n * 80 + f] : Whh[n * 128 + (f - 80)]);
    }
    if (idx < NG / 4) {
        float4 a = bih[idx], b = bhh[idx];
        ((float4*)g_bg)[idx] = make_float4(a.x + b.x, a.y + b.y, a.z + b.z, a.w + b.w);
    }
    // Wrw pack: 268 rows x 128 float4
    if (idx < NRW * 128) {
        int r = idx >> 7, f = idx & 127;
        ((float4*)g_Wrw)[idx] = r4((r < 70) ? Wr[idx] : Ww[(r - 70) * 128 + f]);
    }
    if (idx < NRW) g_brw[idx] = (idx < 70) ? br[idx] : bw[idx - 70];
    if (idx < Bb * Mm / 4) rv_zero[idx] = make_float4(0.f, 0.f, 0.f, 0.f);
    // A1 concat: Bb rows x 208 float4 (64 x | 16 prev_read | 128 h)
    if (idx < Bb * 208) {
        int b = idx / 208, f = idx - b * 208;
        float4 v;
        if (f < 64)      v = x[b * 64 + f];
        else if (f < 80) v = prev_read[b * 16 + (f - 64)];
        else             v = h[b * 128 + (f - 80)];
        ((float4*)g_A1)[idx] = r4(v);
    }
    // Wo rounded copy: 256 rows x 144 float4
    if (idx < 256 * 144) {
        ((float4*)g_Wo)[idx] = r4(Wo[idx]);
    }
}

__global__ void prep_A2(const float4* __restrict__ h_new, const float4* __restrict__ read_vec) {
    int idx = blockIdx.x * blockDim.x + threadIdx.x;
    if (idx >= Bb * 144) return;   // 576/4
    int b = idx / 144, f = idx - b * 144;
    ((float4*)g_A2)[idx] = r4((f < 128) ? h_new[b * 128 + f] : read_vec[b * 16 + (f - 128)]);
}

// ------------------------- tf32 tensor-core GEMM (cp.async 4-stage) ---------
// C[M,N] = A[M,K] @ W[N,K]^T + bias.  tile 64x64, 256 threads (8 warps,
// 2x4 warp grid, 32x16 per warp), BK=16, 4-stage cp.async pipeline.
// A and W must be PRE-ROUNDED to tf32.  M%64==0, K%16==0, N even.

#define STAGES 4
#define STAGE_BYTES 5120   // 64*20*4

__device__ __forceinline__ void mma_tf32(float* c, const uint32_t* a,
                                         uint32_t b0, uint32_t b1) {
    asm volatile(
        "mma.sync.aligned.m16n8k8.row.col.f32.tf32.tf32.f32 "
        "{%0,%1,%2,%3}, {%4,%5,%6,%7}, {%8,%9}, {%0,%1,%2,%3};\n"
        : "+f"(c[0]), "+f"(c[1]), "+f"(c[2]), "+f"(c[3])
        : "r"(a[0]), "r"(a[1]), "r"(a[2]), "r"(a[3]), "r"(b0), "r"(b1));
}

__device__ __forceinline__ void cp16(uint32_t dst, const float* src, int sz) {
    asm volatile("cp.async.ca.shared.global [%0], [%1], 16, %2;\n"
                 :: "r"(dst), "l"(src), "r"(sz));
}

__global__ void __launch_bounds__(256, 2)
gemm_tf32(const float* __restrict__ A, const float* __restrict__ W,
          const float* __restrict__ bias, float* __restrict__ C,
          int M, int N, int K) {
    __shared__ float As[STAGES][64][20];
    __shared__ float Bs[STAGES][64][20];
    int bm = blockIdx.y * 64, bn = blockIdx.x * 64;
    int tid = threadIdx.x;
    int wid = tid >> 5, lane = tid & 31;
    int wm = (wid & 1) * 32, wn = (wid >> 1) * 16;
    int gid = lane >> 2, tig = lane & 3;

    // global->smem mapping: thread -> (row r, 4 consecutive k at c4)
    int r = tid >> 2;            // 0..63
    int c4 = (tid & 3) << 2;     // 0,4,8,12
    const float* Ap = A + (size_t)(bm + r) * K + c4;
    bool wvalid = (bn + r) < N;
    int wsz = wvalid ? 16 : 0;
    const float* Wp = W + (size_t)(wvalid ? (bn + r) : 0) * K + c4;

    uint32_t aDst = (uint32_t)__cvta_generic_to_shared(&As[0][r][c4]);
    uint32_t bDst = (uint32_t)__cvta_generic_to_shared(&Bs[0][r][c4]);

    float acc[2][2][4];
#pragma unroll
    for (int i = 0; i < 2; i++)
#pragma unroll
        for (int j = 0; j < 2; j++)
#pragma unroll
            for (int q = 0; q < 4; q++) acc[i][j][q] = 0.f;

    int numK = K >> 4;

    // prologue: issue stages 0..STAGES-2
#pragma unroll
    for (int s = 0; s < STAGES - 1; s++) {
        if (s < numK) {
            cp16(aDst + s * STAGE_BYTES, Ap + s * 16, 16);
            cp16(bDst + s * STAGE_BYTES, Wp + s * 16, wsz);
        }
        asm volatile("cp.async.commit_group;\n");
    }

    for (int kt = 0; kt < numK; kt++) {
        asm volatile("cp.async.wait_group %0;\n" :: "n"(STAGES - 2));
        __syncthreads();

        // issue stage kt+STAGES-1 (overwrites stage kt-1, all threads past it)
        int kn = kt + STAGES - 1;
        if (kn < numK) {
            int s = kn & (STAGES - 1);
            cp16(aDst + s * STAGE_BYTES, Ap + kn * 16, 16);
            cp16(bDst + s * STAGE_BYTES, Wp + kn * 16, wsz);
        }
        asm volatile("cp.async.commit_group;\n");

        int st = kt & (STAGES - 1);
#pragma unroll
        for (int kk = 0; kk < 16; kk += 8) {
            uint32_t af[2][4];
#pragma unroll
            for (int i = 0; i < 2; i++) {
                int r0 = wm + i * 16 + gid;
                af[i][0] = __float_as_uint(As[st][r0][kk + tig]);
                af[i][1] = __float_as_uint(As[st][r0 + 8][kk + tig]);
                af[i][2] = __float_as_uint(As[st][r0][kk + tig + 4]);
                af[i][3] = __float_as_uint(As[st][r0 + 8][kk + tig + 4]);
            }
#pragma unroll
            for (int j = 0; j < 2; j++) {
                int c0 = wn + j * 8 + gid;
                uint32_t b0 = __float_as_uint(Bs[st][c0][kk + tig]);
                uint32_t b1 = __float_as_uint(Bs[st][c0][kk + tig + 4]);
#pragma unroll
                for (int i = 0; i < 2; i++) mma_tf32(acc[i][j], af[i], b0, b1);
            }
        }
    }

#pragma unroll
    for (int i = 0; i < 2; i++) {
        int row = bm + wm + i * 16 + gid;
#pragma unroll
        for (int j = 0; j < 2; j++) {
            int col = bn + wn + j * 8 + tig * 2;
            if (col < N) {
                float b0 = bias[col], b1 = bias[col + 1];
                C[(size_t)row * N + col]           = acc[i][j][0] + b0;
                C[(size_t)row * N + col + 1]       = acc[i][j][1] + b1;
                C[(size_t)(row + 8) * N + col]     = acc[i][j][2] + b0;
                C[(size_t)(row + 8) * N + col + 1] = acc[i][j][3] + b1;
            }
        }
    }
}

// ------------------------- LSTM pointwise (float4) ---------------------------

__global__ void lstm_pw(const float4* __restrict__ c_in,
                        float4* __restrict__ h_out, float4* __restrict__ c_out) {
    int idx = blockIdx.x * blockDim.x + threadIdx.x;
    if (idx >= Bb * CS / 4) return;
    int b = idx >> 7, q = idx & 127;
    const float* g = g_gates + (size_t)b * NG + q * 4;
    float4 i4 = *(const float4*)(g);
    float4 f4 = *(const float4*)(g + 512);
    float4 g4 = *(const float4*)(g + 1024);
    float4 o4 = *(const float4*)(g + 1536);
    float4 cv = c_in[idx];
    float4 cn, hn;
    cn.x = sigm(f4.x) * cv.x + sigm(i4.x) * ftanh(g4.x);
    cn.y = sigm(f4.y) * cv.y + sigm(i4.y) * ftanh(g4.y);
    cn.z = sigm(f4.z) * cv.z + sigm(i4.z) * ftanh(g4.z);
    cn.w = sigm(f4.w) * cv.w + sigm(i4.w) * ftanh(g4.w);
    hn.x = sigm(o4.x) * ftanh(cn.x);
    hn.y = sigm(o4.y) * ftanh(cn.y);
    hn.z = sigm(o4.z) * ftanh(cn.z);
    hn.w = sigm(o4.w) * ftanh(cn.w);
    c_out[idx] = cn;
    h_out[idx] = hn;
    ((float4*)g_h32)[idx] = r4(hn);   // tf32-rounded copy for addressing GEMM
}

// ------------------------- similarity pass (1 read of memory) ---------------

__global__ void sim_kernel(const float* __restrict__ mem) {
    int b = blockIdx.y;
    int n0 = blockIdx.x * 64;
    __shared__ float kr[64], kw[64];
    __shared__ float nrm[2];
    int t = threadIdx.x;
    const float* base = g_rw + (size_t)b * NRW;
    if (t < 64)       kr[t] = base[t];
    else if (t < 128) kw[t - 64] = base[70 + (t - 64)];
    __syncthreads();
    if (t == 0) {
        float s = 0.f;
        for (int i = 0; i < 64; i++) s += kr[i] * kr[i];
        nrm[0] = sqrtf(s) + 1e-8f;
    } else if (t == 32) {
        float s = 0.f;
        for (int i = 0; i < 64; i++) s += kw[i] * kw[i];
        nrm[1] = sqrtf(s) + 1e-8f;
    }
    __syncthreads();
    int mg = t & 15, rg = t >> 4;
    float4 kr4 = *(const float4*)&kr[mg * 4];
    float4 kw4 = *(const float4*)&kw[mg * 4];
#pragma unroll
    for (int i = 0; i < 4; i++) {
        int n = n0 + i * 16 + rg;
        size_t ro = (size_t)b * Nn + n;
        float4 m4 = *(const float4*)(mem + ro * 64 + mg * 4);
        float dr = m4.x * kr4.x + m4.y * kr4.y + m4.z * kr4.z + m4.w * kr4.w;
        float dw = m4.x * kw4.x + m4.y * kw4.y + m4.z * kw4.z + m4.w * kw4.w;
        float sq = m4.x * m4.x + m4.y * m4.y + m4.z * m4.z + m4.w * m4.w;
#pragma unroll
        for (int off = 8; off; off >>= 1) {
            dr += __shfl_xor_sync(0xffffffffu, dr, off);
            dw += __shfl_xor_sync(0xffffffffu, dw, off);
            sq += __shfl_xor_sync(0xffffffffu, sq, off);
        }
        if (mg == 0) {
            float nm = sqrtf(sq) + 1e-8f;
            g_sim_r[ro] = dr / (nrm[0] * nm);
            g_sim_w[ro] = dw / (nrm[1] * nm);
        }
    }
}

// ------------------------- addressing ---------------------------------------

__global__ void addressing_kernel(const float* __restrict__ read_w_prev,
                                  const float* __restrict__ write_w_prev,
                                  float* __restrict__ w_read, float* __restrict__ w_write) {
    int b = blockIdx.x & 255;
    bool isw = blockIdx.x >= 256;
    const float* ov = g_rw + (size_t)b * NRW + (isw ? 70 : 0);
    const float* sim = (isw ? g_sim_w : g_sim_r) + (size_t)b * Nn;
    const float* prev = (isw ? write_w_prev : read_w_prev) + (size_t)b * Nn;
    float* wout = (isw ? w_write : w_read) + (size_t)b * Nn;

    __shared__ float wg[Nn];
    __shared__ float red[256];
    int t = threadIdx.x;

    float beta  = softplus(ov[64]);
    float g     = sigm(ov[65]);
    float s0 = ov[66], s1 = ov[67], s2 = ov[68];
    float smax = fmaxf(s0, fmaxf(s1, s2));
    float e0 = __expf(s0 - smax), e1 = __expf(s1 - smax), e2 = __expf(s2 - smax);
    float es = e0 + e1 + e2;
    e0 /= es; e1 /= es; e2 /= es;
    float gamma = 1.f + softplus(ov[69]);

    float loc[8];
    float mx = -1e30f;
#pragma unroll
    for (int i = 0; i < 8; i++) {
        float v = beta * sim[t + i * 256];
        loc[i] = v;
        mx = fmaxf(mx, v);
    }
    red[t] = mx; __syncthreads();
    for (int off = 128; off; off >>= 1) {
        if (t < off) red[t] = fmaxf(red[t], red[t + off]);
        __syncthreads();
    }
    mx = red[0]; __syncthreads();
    float sum = 0.f;
#pragma unroll
    for (int i = 0; i < 8; i++) { loc[i] = __expf(loc[i] - mx); sum += loc[i]; }
    red[t] = sum; __syncthreads();
    for (int off = 128; off; off >>= 1) {
        if (t < off) red[t] += red[t + off];
        __syncthreads();
    }
    float inv = 1.f / red[0]; __syncthreads();
#pragma unroll
    for (int i = 0; i < 8; i++) {
        int n = t + i * 256;
        wg[n] = g * loc[i] * inv + (1.f - g) * prev[n];
    }
    __syncthreads();

    float ws[8];
    float sum2 = 0.f;
#pragma unroll
    for (int i = 0; i < 8; i++) {
        int n = t + i * 256;
        float v = e0 * wg[(n + Nn - 1) & (Nn - 1)] + e1 * wg[n] + e2 * wg[(n + 1) & (Nn - 1)];
        v = __powf(v, gamma);
        ws[i] = v;
        sum2 += v;
    }
    red[t] = sum2; __syncthreads();
    for (int off = 128; off; off >>= 1) {
        if (t < off) red[t] += red[t + off];
        __syncthreads();
    }
    float inv2 = 1.f / (red[0] + 1e-8f);
#pragma unroll
    for (int i = 0; i < 8; i++) wout[t + i * 256] = ws[i] * inv2;
}

// ------------------------- memory update + read_vec -------------------------
// Reversed block order: sim_kernel just streamed memory through L2; reading
// back-to-front maximizes L2 hits on the recently-touched tail.

__global__ void update_kernel(const float* __restrict__ mem,
                              const float* __restrict__ w_read,
                              const float* __restrict__ w_write,
                              float* __restrict__ mem_out,
                              float* __restrict__ read_vec) {
    int nblk = gridDim.x - 1 - blockIdx.x;
    int b    = gridDim.y - 1 - blockIdx.y;
    int n0 = nblk * 128;
    __shared__ float er[64], ad[64];
    int t = threadIdx.x;
    const float* wo = g_rw + (size_t)b * NRW;
    if (t < 64) {
        er[t] = sigm(wo[140 + t]);  // 70 + (M+6)
        ad[t] = wo[204 + t];        // 70 + (2M+6)
    }
    __syncthreads();
    int mg = t & 15, rg = t >> 4;
    float4 e4 = *(const float4*)&er[mg * 4];
    float4 a4 = *(const float4*)&ad[mg * 4];
    float4 acc = make_float4(0.f, 0.f, 0.f, 0.f);
#pragma unroll
    for (int i = 0; i < 8; i++) {
        int n = n0 + i * 16 + rg;
        size_t ro = (size_t)b * Nn + n;
        float ww = w_write[ro];
        float wr = w_read[ro];
        float4 m4 = *(const float4*)(mem + ro * 64 + mg * 4);
        float4 o;
        o.x = m4.x * (1.f - ww * e4.x) + ww * a4.x;
        o.y = m4.y * (1.f - ww * e4.y) + ww * a4.y;
        o.z = m4.z * (1.f - ww * e4.z) + ww * a4.z;
        o.w = m4.w * (1.f - ww * e4.w) + ww * a4.w;
        *(float4*)(mem_out + ro * 64 + mg * 4) = o;
        acc.x += wr * m4.x; acc.y += wr * m4.y;
        acc.z += wr * m4.z; acc.w += wr * m4.w;
    }
    float* rv = read_vec + (size_t)b * Mm + mg * 4;
    atomicAdd(rv + 0, acc.x);
    atomicAdd(rv + 1, acc.y);
    atomicAdd(rv + 2, acc.z);
    atomicAdd(rv + 3, acc.w);
}

// ---------------------------------------------------------------------------

extern "C" void kernel_launch(void* const* d_in, const int* in_sizes, int n_in,
                              void* d_out, int out_size) {
    const float* x         = (const float*)d_in[0];
    const float* memory    = (const float*)d_in[1];
    const float* h         = (const float*)d_in[2];
    const float* c         = (const float*)d_in[3];
    const float* read_w    = (const float*)d_in[4];
    const float* write_w   = (const float*)d_in[5];
    const float* prev_read = (const float*)d_in[6];
    const float* W_ih      = (const float*)d_in[7];
    const float* W_hh      = (const float*)d_in[8];
    const float* b_ih      = (const float*)d_in[9];
    const float* b_hh      = (const float*)d_in[10];
    const float* W_r       = (const float*)d_in[11];
    const float* b_r       = (const float*)d_in[12];
    const float* W_w       = (const float*)d_in[13];
    const float* b_w       = (const float*)d_in[14];
    const float* W_o       = (const float*)d_in[15];
    const float* b_o       = (const float*)d_in[16];

    float* out  = (float*)d_out;
    float* o_out = out + OFF_OUT;
    float* o_mem = out + OFF_MEM;
    float* o_h   = out + OFF_H;
    float* o_c   = out + OFF_C;
    float* o_wr  = out + OFF_WR;
    float* o_ww  = out + OFF_WW;
    float* o_rv  = out + OFF_RV;

    float *A1, *Wg, *bg, *gates, *Wrw, *brw, *A2, *rw, *Wo, *h32;
    cudaGetSymbolAddress((void**)&A1,    g_A1);
    cudaGetSymbolAddress((void**)&Wg,    g_Wg);
    cudaGetSymbolAddress((void**)&bg,    g_bg);
    cudaGetSymbolAddress((void**)&gates, g_gates);
    cudaGetSymbolAddress((void**)&Wrw,   g_Wrw);
    cudaGetSymbolAddress((void**)&brw,   g_brw);
    cudaGetSymbolAddress((void**)&A2,    g_A2);
    cudaGetSymbolAddress((void**)&rw,    g_rw);
    cudaGetSymbolAddress((void**)&Wo,    g_Wo);
    cudaGetSymbolAddress((void**)&h32,   g_h32);

    // 1. weight packing + input concat + rv zero (tf32-rounded)
    prep_all<<<(NG * 208 + 255) / 256, 256>>>(
        (const float4*)W_ih, (const float4*)W_hh, (const float4*)b_ih,
        (const float4*)b_hh, (const float4*)W_r, b_r, (const float4*)W_w, b_w,
        (const float4*)x, (const float4*)prev_read, (const float4*)h,
        (const float4*)W_o, (float4*)o_rv);
    // 2. gates GEMM  [256,832] x [2048,832]^T  (tf32 MMA, cp.async)
    gemm_tf32<<<dim3(NG / 64, Bb / 64), 256>>>(A1, Wg, bg, gates, Bb, NG, KG);
    // 3. LSTM pointwise -> h_new, c_new (+ rounded h copy)
    lstm_pw<<<(Bb * CS / 4 + 255) / 256, 256>>>((const float4*)c,
                                                (float4*)o_h, (float4*)o_c);
    // 4. addressing GEMM  h_new x [268,512]^T
    gemm_tf32<<<dim3((NRW + 63) / 64, Bb / 64), 256>>>(h32, Wrw, brw, rw, Bb, NRW, CS);
    // 5. similarity pass (single read of memory)
    sim_kernel<<<dim3(Nn / 64, Bb), 256>>>(memory);
    // 6. addressing (read + write heads)
    addressing_kernel<<<512, 256>>>(read_w, write_w, o_wr, o_ww);
    // 7. memory update + read_vec (reverse order for L2 reuse)
    update_kernel<<<dim3(Nn / 128, Bb), 256>>>(memory, o_wr, o_ww, o_mem, o_rv);
    // 8. concat [h_new | read_vec] (rounded)
    prep_A2<<<(Bb * 144 + 255) / 256, 256>>>((const float4*)o_h, (const float4*)o_rv);
    // 9. output GEMM
    gemm_tf32<<<dim3(256 / 64, Bb / 64), 256>>>(A2, Wo, b_o, o_out, Bb, 256, KO);
}

// round 6
// speedup vs baseline: 2.1819x; 1.0674x over previous
#include <cuda_runtime.h>
#include <cstdint>
#include <cstddef>

// ---------------------------------------------------------------------------
// NTM single step.  B=256, N=2048, M=64, CS=512, INP=256, OUT=256
// ---------------------------------------------------------------------------

#define Bb 256
#define Nn 2048
#define Mm 64
#define CS 512
#define KG 832      // INP + M + CS
#define NG 2048     // 4*CS
#define NRW 268     // ADDR_R(70) + ADDR_W(198)
#define KO 576      // CS + M

// output offsets (elements)
#define OFF_OUT 0
#define OFF_MEM 65536
#define OFF_H   33619968
#define OFF_C   33751040
#define OFF_WR  33882112
#define OFF_WW  34406400
#define OFF_RV  34930688

// scratch (all GEMM operands pre-rounded to tf32 by producers)
__device__ float g_A1[Bb * KG];
__device__ float g_Wg[NG * KG];
__device__ float g_gates[Bb * NG];
__device__ float g_Wrw[NRW * CS];
__device__ float g_rw[Bb * NRW];
__device__ float g_sim_r[Bb * Nn];
__device__ float g_sim_w[Bb * Nn];
__device__ float g_A2[Bb * KO];
__device__ float g_Wo[256 * KO];
__device__ float g_h32[Bb * CS];

__device__ __forceinline__ float sigm(float x) { return 1.f / (1.f + __expf(-x)); }
__device__ __forceinline__ float ftanh(float x) {
    float e = __expf(2.f * x);
    return (e - 1.f) / (e + 1.f);
}
__device__ __forceinline__ float softplus(float x) { return x > 20.f ? x : log1pf(expf(x)); }
__device__ __forceinline__ float to_tf32(float x) {
    float r; asm("cvt.rna.tf32.f32 %0, %1;" : "=f"(r) : "f"(x)); return r;
}
__device__ __forceinline__ float4 r4(float4 v) {
    return make_float4(to_tf32(v.x), to_tf32(v.y), to_tf32(v.z), to_tf32(v.w));
}

// ------------------------- combined prep (float4, tf32-rounded) --------------
// Also bias-initializes the split-K GEMM accumulator buffers:
//   g_gates <- bih+bhh,  g_rw <- [br|bw],  o_out <- b_o.

__global__ void prep_all(const float4* __restrict__ Wih, const float4* __restrict__ Whh,
                         const float* __restrict__ bih, const float* __restrict__ bhh,
                         const float4* __restrict__ Wr,  const float* __restrict__ br,
                         const float4* __restrict__ Ww,  const float* __restrict__ bw,
                         const float4* __restrict__ x,   const float4* __restrict__ prev_read,
                         const float4* __restrict__ h,   const float4* __restrict__ Wo,
                         const float* __restrict__ bo,
                         float4* __restrict__ rv_zero,   float* __restrict__ o_out) {
    int idx = blockIdx.x * blockDim.x + threadIdx.x;
    // Wg pack: NG rows x 208 float4 (80 from Wih, 128 from Whh)
    if (idx < NG * 208) {
        int n = idx / 208, f = idx - n * 208;
        ((float4*)g_Wg)[idx] = r4((f < 80) ? Wih[n * 80 + f] : Whh[n * 128 + (f - 80)]);
    }
    // g_gates bias init: Bb x NG
    if (idx < Bb * NG) {
        int j = idx & (NG - 1);
        g_gates[idx] = bih[j] + bhh[j];
    }
    // Wrw pack: 268 rows x 128 float4
    if (idx < NRW * 128) {
        int r = idx >> 7, f = idx & 127;
        ((float4*)g_Wrw)[idx] = r4((r < 70) ? Wr[idx] : Ww[(r - 70) * 128 + f]);
    }
    // g_rw bias init: Bb x NRW
    if (idx < Bb * NRW) {
        int j = idx % NRW;
        g_rw[idx] = (j < 70) ? br[j] : bw[j - 70];
    }
    // o_out bias init: Bb x 256
    if (idx < Bb * 256) {
        o_out[idx] = bo[idx & 255];
    }
    if (idx < Bb * Mm / 4) rv_zero[idx] = make_float4(0.f, 0.f, 0.f, 0.f);
    // A1 concat: Bb rows x 208 float4 (64 x | 16 prev_read | 128 h)
    if (idx < Bb * 208) {
        int b = idx / 208, f = idx - b * 208;
        float4 v;
        if (f < 64)      v = x[b * 64 + f];
        else if (f < 80) v = prev_read[b * 16 + (f - 64)];
        else             v = h[b * 128 + (f - 80)];
        ((float4*)g_A1)[idx] = r4(v);
    }
    // Wo rounded copy: 256 rows x 144 float4
    if (idx < 256 * 144) {
        ((float4*)g_Wo)[idx] = r4(Wo[idx]);
    }
}

__global__ void prep_A2(const float4* __restrict__ h_new, const float4* __restrict__ read_vec) {
    int idx = blockIdx.x * blockDim.x + threadIdx.x;
    if (idx >= Bb * 144) return;   // 576/4
    int b = idx / 144, f = idx - b * 144;
    ((float4*)g_A2)[idx] = r4((f < 128) ? h_new[b * 128 + f] : read_vec[b * 16 + (f - 128)]);
}

// ------------------------- tf32 tensor-core GEMM (cp.async, split-K) --------
// C += A[M,K] @ W[N,K]^T  over K-range [z*Ksub, (z+1)*Ksub), atomic epilogue.
// C must be pre-initialized with bias.  tile 64x64, 256 threads (8 warps),
// BK=16, 4-stage cp.async.  A and W PRE-ROUNDED to tf32.  M%64==0, Ksub%16==0.

#define STAGES 4
#define STAGE_BYTES 5120   // 64*20*4

__device__ __forceinline__ void mma_tf32(float* c, const uint32_t* a,
                                         uint32_t b0, uint32_t b1) {
    asm volatile(
        "mma.sync.aligned.m16n8k8.row.col.f32.tf32.tf32.f32 "
        "{%0,%1,%2,%3}, {%4,%5,%6,%7}, {%8,%9}, {%0,%1,%2,%3};\n"
        : "+f"(c[0]), "+f"(c[1]), "+f"(c[2]), "+f"(c[3])
        : "r"(a[0]), "r"(a[1]), "r"(a[2]), "r"(a[3]), "r"(b0), "r"(b1));
}

__device__ __forceinline__ void cp16(uint32_t dst, const float* src, int sz) {
    asm volatile("cp.async.ca.shared.global [%0], [%1], 16, %2;\n"
                 :: "r"(dst), "l"(src), "r"(sz));
}

__global__ void __launch_bounds__(256, 2)
gemm_tf32(const float* __restrict__ A, const float* __restrict__ W,
          float* __restrict__ C, int M, int N, int K, int Ksub) {
    __shared__ float As[STAGES][64][20];
    __shared__ float Bs[STAGES][64][20];
    int bm = blockIdx.y * 64, bn = blockIdx.x * 64;
    int kOff = blockIdx.z * Ksub;
    int tid = threadIdx.x;
    int wid = tid >> 5, lane = tid & 31;
    int wm = (wid & 1) * 32, wn = (wid >> 1) * 16;
    int gid = lane >> 2, tig = lane & 3;

    // global->smem mapping: thread -> (row r, 4 consecutive k at c4)
    int r = tid >> 2;            // 0..63
    int c4 = (tid & 3) << 2;     // 0,4,8,12
    const float* Ap = A + (size_t)(bm + r) * K + kOff + c4;
    bool wvalid = (bn + r) < N;
    int wsz = wvalid ? 16 : 0;
    const float* Wp = W + (size_t)(wvalid ? (bn + r) : 0) * K + kOff + c4;

    uint32_t aDst = (uint32_t)__cvta_generic_to_shared(&As[0][r][c4]);
    uint32_t bDst = (uint32_t)__cvta_generic_to_shared(&Bs[0][r][c4]);

    float acc[2][2][4];
#pragma unroll
    for (int i = 0; i < 2; i++)
#pragma unroll
        for (int j = 0; j < 2; j++)
#pragma unroll
            for (int q = 0; q < 4; q++) acc[i][j][q] = 0.f;

    int numK = Ksub >> 4;

    // prologue: issue stages 0..STAGES-2
#pragma unroll
    for (int s = 0; s < STAGES - 1; s++) {
        if (s < numK) {
            cp16(aDst + s * STAGE_BYTES, Ap + s * 16, 16);
            cp16(bDst + s * STAGE_BYTES, Wp + s * 16, wsz);
        }
        asm volatile("cp.async.commit_group;\n");
    }

    for (int kt = 0; kt < numK; kt++) {
        asm volatile("cp.async.wait_group %0;\n" :: "n"(STAGES - 2));
        __syncthreads();

        int kn = kt + STAGES - 1;
        if (kn < numK) {
            int s = kn & (STAGES - 1);
            cp16(aDst + s * STAGE_BYTES, Ap + kn * 16, 16);
            cp16(bDst + s * STAGE_BYTES, Wp + kn * 16, wsz);
        }
        asm volatile("cp.async.commit_group;\n");

        int st = kt & (STAGES - 1);
#pragma unroll
        for (int kk = 0; kk < 16; kk += 8) {
            uint32_t af[2][4];
#pragma unroll
            for (int i = 0; i < 2; i++) {
                int r0 = wm + i * 16 + gid;
                af[i][0] = __float_as_uint(As[st][r0][kk + tig]);
                af[i][1] = __float_as_uint(As[st][r0 + 8][kk + tig]);
                af[i][2] = __float_as_uint(As[st][r0][kk + tig + 4]);
                af[i][3] = __float_as_uint(As[st][r0 + 8][kk + tig + 4]);
            }
#pragma unroll
            for (int j = 0; j < 2; j++) {
                int c0 = wn + j * 8 + gid;
                uint32_t b0 = __float_as_uint(Bs[st][c0][kk + tig]);
                uint32_t b1 = __float_as_uint(Bs[st][c0][kk + tig + 4]);
#pragma unroll
                for (int i = 0; i < 2; i++) mma_tf32(acc[i][j], af[i], b0, b1);
            }
        }
    }

    // atomic-accumulate epilogue (C pre-initialized with bias)
#pragma unroll
    for (int i = 0; i < 2; i++) {
        int row = bm + wm + i * 16 + gid;
#pragma unroll
        for (int j = 0; j < 2; j++) {
            int col = bn + wn + j * 8 + tig * 2;
            if (col < N) {
                atomicAdd(&C[(size_t)row * N + col],           acc[i][j][0]);
                atomicAdd(&C[(size_t)row * N + col + 1],       acc[i][j][1]);
                atomicAdd(&C[(size_t)(row + 8) * N + col],     acc[i][j][2]);
                atomicAdd(&C[(size_t)(row + 8) * N + col + 1], acc[i][j][3]);
            }
        }
    }
}

// ------------------------- LSTM pointwise (float4) ---------------------------

__global__ void lstm_pw(const float4* __restrict__ c_in,
                        float4* __restrict__ h_out, float4* __restrict__ c_out) {
    int idx = blockIdx.x * blockDim.x + threadIdx.x;
    if (idx >= Bb * CS / 4) return;
    int b = idx >> 7, q = idx & 127;
    const float* g = g_gates + (size_t)b * NG + q * 4;
    float4 i4 = *(const float4*)(g);
    float4 f4 = *(const float4*)(g + 512);
    float4 g4 = *(const float4*)(g + 1024);
    float4 o4 = *(const float4*)(g + 1536);
    float4 cv = c_in[idx];
    float4 cn, hn;
    cn.x = sigm(f4.x) * cv.x + sigm(i4.x) * ftanh(g4.x);
    cn.y = sigm(f4.y) * cv.y + sigm(i4.y) * ftanh(g4.y);
    cn.z = sigm(f4.z) * cv.z + sigm(i4.z) * ftanh(g4.z);
    cn.w = sigm(f4.w) * cv.w + sigm(i4.w) * ftanh(g4.w);
    hn.x = sigm(o4.x) * ftanh(cn.x);
    hn.y = sigm(o4.y) * ftanh(cn.y);
    hn.z = sigm(o4.z) * ftanh(cn.z);
    hn.w = sigm(o4.w) * ftanh(cn.w);
    c_out[idx] = cn;
    h_out[idx] = hn;
    ((float4*)g_h32)[idx] = r4(hn);   // tf32-rounded copy for addressing GEMM
}

// ------------------------- similarity pass (1 read of memory) ---------------

__global__ void sim_kernel(const float* __restrict__ mem) {
    int b = blockIdx.y;
    int n0 = blockIdx.x * 64;
    __shared__ float kr[64], kw[64];
    __shared__ float nrm[2];
    int t = threadIdx.x;
    const float* base = g_rw + (size_t)b * NRW;
    if (t < 64)       kr[t] = base[t];
    else if (t < 128) kw[t - 64] = base[70 + (t - 64)];
    __syncthreads();
    if (t == 0) {
        float s = 0.f;
        for (int i = 0; i < 64; i++) s += kr[i] * kr[i];
        nrm[0] = sqrtf(s) + 1e-8f;
    } else if (t == 32) {
        float s = 0.f;
        for (int i = 0; i < 64; i++) s += kw[i] * kw[i];
        nrm[1] = sqrtf(s) + 1e-8f;
    }
    __syncthreads();
    int mg = t & 15, rg = t >> 4;
    float4 kr4 = *(const float4*)&kr[mg * 4];
    float4 kw4 = *(const float4*)&kw[mg * 4];
#pragma unroll
    for (int i = 0; i < 4; i++) {
        int n = n0 + i * 16 + rg;
        size_t ro = (size_t)b * Nn + n;
        float4 m4 = *(const float4*)(mem + ro * 64 + mg * 4);
        float dr = m4.x * kr4.x + m4.y * kr4.y + m4.z * kr4.z + m4.w * kr4.w;
        float dw = m4.x * kw4.x + m4.y * kw4.y + m4.z * kw4.z + m4.w * kw4.w;
        float sq = m4.x * m4.x + m4.y * m4.y + m4.z * m4.z + m4.w * m4.w;
#pragma unroll
        for (int off = 8; off; off >>= 1) {
            dr += __shfl_xor_sync(0xffffffffu, dr, off);
            dw += __shfl_xor_sync(0xffffffffu, dw, off);
            sq += __shfl_xor_sync(0xffffffffu, sq, off);
        }
        if (mg == 0) {
            float nm = sqrtf(sq) + 1e-8f;
            g_sim_r[ro] = dr / (nrm[0] * nm);
            g_sim_w[ro] = dw / (nrm[1] * nm);
        }
    }
}

// ------------------------- addressing ---------------------------------------

__global__ void addressing_kernel(const float* __restrict__ read_w_prev,
                                  const float* __restrict__ write_w_prev,
                                  float* __restrict__ w_read, float* __restrict__ w_write) {
    int b = blockIdx.x & 255;
    bool isw = blockIdx.x >= 256;
    const float* ov = g_rw + (size_t)b * NRW + (isw ? 70 : 0);
    const float* sim = (isw ? g_sim_w : g_sim_r) + (size_t)b * Nn;
    const float* prev = (isw ? write_w_prev : read_w_prev) + (size_t)b * Nn;
    float* wout = (isw ? w_write : w_read) + (size_t)b * Nn;

    __shared__ float wg[Nn];
    __shared__ float red[256];
    int t = threadIdx.x;

    float beta  = softplus(ov[64]);
    float g     = sigm(ov[65]);
    float s0 = ov[66], s1 = ov[67], s2 = ov[68];
    float smax = fmaxf(s0, fmaxf(s1, s2));
    float e0 = __expf(s0 - smax), e1 = __expf(s1 - smax), e2 = __expf(s2 - smax);
    float es = e0 + e1 + e2;
    e0 /= es; e1 /= es; e2 /= es;
    float gamma = 1.f + softplus(ov[69]);

    float loc[8];
    float mx = -1e30f;
#pragma unroll
    for (int i = 0; i < 8; i++) {
        float v = beta * sim[t + i * 256];
        loc[i] = v;
        mx = fmaxf(mx, v);
    }
    red[t] = mx; __syncthreads();
    for (int off = 128; off; off >>= 1) {
        if (t < off) red[t] = fmaxf(red[t], red[t + off]);
        __syncthreads();
    }
    mx = red[0]; __syncthreads();
    float sum = 0.f;
#pragma unroll
    for (int i = 0; i < 8; i++) { loc[i] = __expf(loc[i] - mx); sum += loc[i]; }
    red[t] = sum; __syncthreads();
    for (int off = 128; off; off >>= 1) {
        if (t < off) red[t] += red[t + off];
        __syncthreads();
    }
    float inv = 1.f / red[0]; __syncthreads();
#pragma unroll
    for (int i = 0; i < 8; i++) {
        int n = t + i * 256;
        wg[n] = g * loc[i] * inv + (1.f - g) * prev[n];
    }
    __syncthreads();

    float ws[8];
    float sum2 = 0.f;
#pragma unroll
    for (int i = 0; i < 8; i++) {
        int n = t + i * 256;
        float v = e0 * wg[(n + Nn - 1) & (Nn - 1)] + e1 * wg[n] + e2 * wg[(n + 1) & (Nn - 1)];
        v = __powf(v, gamma);
        ws[i] = v;
        sum2 += v;
    }
    red[t] = sum2; __syncthreads();
    for (int off = 128; off; off >>= 1) {
        if (t < off) red[t] += red[t + off];
        __syncthreads();
    }
    float inv2 = 1.f / (red[0] + 1e-8f);
#pragma unroll
    for (int i = 0; i < 8; i++) wout[t + i * 256] = ws[i] * inv2;
}

// ------------------------- memory update + read_vec -------------------------

__global__ void update_kernel(const float* __restrict__ mem,
                              const float* __restrict__ w_read,
                              const float* __restrict__ w_write,
                              float* __restrict__ mem_out,
                              float* __restrict__ read_vec) {
    int nblk = gridDim.x - 1 - blockIdx.x;
    int b    = gridDim.y - 1 - blockIdx.y;
    int n0 = nblk * 128;
    __shared__ float er[64], ad[64];
    int t = threadIdx.x;
    const float* wo = g_rw + (size_t)b * NRW;
    if (t < 64) {
        er[t] = sigm(wo[140 + t]);  // 70 + (M+6)
        ad[t] = wo[204 + t];        // 70 + (2M+6)
    }
    __syncthreads();
    int mg = t & 15, rg = t >> 4;
    float4 e4 = *(const float4*)&er[mg * 4];
    float4 a4 = *(const float4*)&ad[mg * 4];
    float4 acc = make_float4(0.f, 0.f, 0.f, 0.f);
#pragma unroll
    for (int i = 0; i < 8; i++) {
        int n = n0 + i * 16 + rg;
        size_t ro = (size_t)b * Nn + n;
        float ww = w_write[ro];
        float wr = w_read[ro];
        float4 m4 = *(const float4*)(mem + ro * 64 + mg * 4);
        float4 o;
        o.x = m4.x * (1.f - ww * e4.x) + ww * a4.x;
        o.y = m4.y * (1.f - ww * e4.y) + ww * a4.y;
        o.z = m4.z * (1.f - ww * e4.z) + ww * a4.z;
        o.w = m4.w * (1.f - ww * e4.w) + ww * a4.w;
        *(float4*)(mem_out + ro * 64 + mg * 4) = o;
        acc.x += wr * m4.x; acc.y += wr * m4.y;
        acc.z += wr * m4.z; acc.w += wr * m4.w;
    }
    float* rv = read_vec + (size_t)b * Mm + mg * 4;
    atomicAdd(rv + 0, acc.x);
    atomicAdd(rv + 1, acc.y);
    atomicAdd(rv + 2, acc.z);
    atomicAdd(rv + 3, acc.w);
}

// ---------------------------------------------------------------------------

extern "C" void kernel_launch(void* const* d_in, const int* in_sizes, int n_in,
                              void* d_out, int out_size) {
    const float* x         = (const float*)d_in[0];
    const float* memory    = (const float*)d_in[1];
    const float* h         = (const float*)d_in[2];
    const float* c         = (const float*)d_in[3];
    const float* read_w    = (const float*)d_in[4];
    const float* write_w   = (const float*)d_in[5];
    const float* prev_read = (const float*)d_in[6];
    const float* W_ih      = (const float*)d_in[7];
    const float* W_hh      = (const float*)d_in[8];
    const float* b_ih      = (const float*)d_in[9];
    const float* b_hh      = (const float*)d_in[10];
    const float* W_r       = (const float*)d_in[11];
    const float* b_r       = (const float*)d_in[12];
    const float* W_w       = (const float*)d_in[13];
    const float* b_w       = (const float*)d_in[14];
    const float* W_o       = (const float*)d_in[15];
    const float* b_o       = (const float*)d_in[16];

    float* out  = (float*)d_out;
    float* o_out = out + OFF_OUT;
    float* o_mem = out + OFF_MEM;
    float* o_h   = out + OFF_H;
    float* o_c   = out + OFF_C;
    float* o_wr  = out + OFF_WR;
    float* o_ww  = out + OFF_WW;
    float* o_rv  = out + OFF_RV;

    float *A1, *Wg, *gates, *Wrw, *A2, *rw, *Wo, *h32;
    cudaGetSymbolAddress((void**)&A1,    g_A1);
    cudaGetSymbolAddress((void**)&Wg,    g_Wg);
    cudaGetSymbolAddress((void**)&gates, g_gates);
    cudaGetSymbolAddress((void**)&Wrw,   g_Wrw);
    cudaGetSymbolAddress((void**)&A2,    g_A2);
    cudaGetSymbolAddress((void**)&rw,    g_rw);
    cudaGetSymbolAddress((void**)&Wo,    g_Wo);
    cudaGetSymbolAddress((void**)&h32,   g_h32);

    // 1. weight packing + input concat + bias-init of accumulators
    prep_all<<<(Bb * NG + 255) / 256, 256>>>(
        (const float4*)W_ih, (const float4*)W_hh, b_ih, b_hh,
        (const float4*)W_r, b_r, (const float4*)W_w, b_w,
        (const float4*)x, (const float4*)prev_read, (const float4*)h,
        (const float4*)W_o, b_o, (float4*)o_rv, o_out);
    // 2. gates GEMM  [256,832] x [2048,832]^T  split-K=2 -> 256 CTAs
    gemm_tf32<<<dim3(NG / 64, Bb / 64, 2), 256>>>(A1, Wg, gates, Bb, NG, KG, KG / 2);
    // 3. LSTM pointwise -> h_new, c_new (+ rounded h copy)
    lstm_pw<<<(Bb * CS / 4 + 255) / 256, 256>>>((const float4*)c,
                                                (float4*)o_h, (float4*)o_c);
    // 4. addressing GEMM  h_new x [268,512]^T  split-K=4 -> 80 CTAs
    gemm_tf32<<<dim3((NRW + 63) / 64, Bb / 64, 4), 256>>>(h32, Wrw, rw, Bb, NRW, CS, CS / 4);
    // 5. similarity pass (single read of memory)
    sim_kernel<<<dim3(Nn / 64, Bb), 256>>>(memory);
    // 6. addressing (read + write heads)
    addressing_kernel<<<512, 256>>>(read_w, write_w, o_wr, o_ww);
    // 7. memory update + read_vec (reverse order for L2 reuse)
    update_kernel<<<dim3(Nn / 128, Bb), 256>>>(memory, o_wr, o_ww, o_mem, o_rv);
    // 8. concat [h_new | read_vec] (rounded)
    prep_A2<<<(Bb * 144 + 255) / 256, 256>>>((const float4*)o_h, (const float4*)o_rv);
    // 9. output GEMM  split-K=4 -> 64 CTAs
    gemm_tf32<<<dim3(256 / 64, Bb / 64, 4), 256>>>(A2, Wo, o_out, Bb, 256, KO, KO / 4);
}

// round 7
// speedup vs baseline: 2.9992x; 1.3746x over previous
#include <cuda_runtime.h>
#include <cstdint>
#include <cstddef>

// ---------------------------------------------------------------------------
// NTM single step.  B=256, N=2048, M=64, CS=512, INP=256, OUT=256
// ---------------------------------------------------------------------------

#define Bb 256
#define Nn 2048
#define Mm 64
#define CS 512
#define KG 832      // INP + M + CS
#define NG 2048     // 4*CS
#define NRW 268     // ADDR_R(70) + ADDR_W(198)
#define KO 576      // CS + M

// output offsets (elements)
#define OFF_OUT 0
#define OFF_MEM 65536
#define OFF_H   33619968
#define OFF_C   33751040
#define OFF_WR  33882112
#define OFF_WW  34406400
#define OFF_RV  34930688

// scratch (all GEMM operands pre-rounded to tf32 by producers)
__device__ float g_A1[Bb * KG];
__device__ float g_Wg[NG * KG];
__device__ float g_gates[Bb * NG];
__device__ float g_Wrw[NRW * CS];
__device__ float g_rw[Bb * NRW];
__device__ float g_A2[Bb * KO];
__device__ float g_Wo[256 * KO];
__device__ float g_h32[Bb * CS];

__device__ __forceinline__ float sigm(float x) { return 1.f / (1.f + __expf(-x)); }
__device__ __forceinline__ float ftanh(float x) {
    float e = __expf(2.f * x);
    return (e - 1.f) / (e + 1.f);
}
__device__ __forceinline__ float softplus(float x) { return x > 20.f ? x : log1pf(expf(x)); }
__device__ __forceinline__ float to_tf32(float x) {
    float r; asm("cvt.rna.tf32.f32 %0, %1;" : "=f"(r) : "f"(x)); return r;
}
__device__ __forceinline__ float4 r4(float4 v) {
    return make_float4(to_tf32(v.x), to_tf32(v.y), to_tf32(v.z), to_tf32(v.w));
}

// ------------------------- combined prep (float4, tf32-rounded) --------------
// Also bias-initializes the split-K GEMM accumulator buffers:
//   g_gates <- bih+bhh,  g_rw <- [br|bw],  o_out <- b_o.

__global__ void prep_all(const float4* __restrict__ Wih, const float4* __restrict__ Whh,
                         const float* __restrict__ bih, const float* __restrict__ bhh,
                         const float4* __restrict__ Wr,  const float* __restrict__ br,
                         const float4* __restrict__ Ww,  const float* __restrict__ bw,
                         const float4* __restrict__ x,   const float4* __restrict__ prev_read,
                         const float4* __restrict__ h,   const float4* __restrict__ Wo,
                         const float* __restrict__ bo,   float* __restrict__ o_out) {
    int idx = blockIdx.x * blockDim.x + threadIdx.x;
    // Wg pack: NG rows x 208 float4 (80 from Wih, 128 from Whh)
    if (idx < NG * 208) {
        int n = idx / 208, f = idx - n * 208;
        ((float4*)g_Wg)[idx] = r4((f < 80) ? Wih[n * 80 + f] : Whh[n * 128 + (f - 80)]);
    }
    // g_gates bias init: Bb x NG
    if (idx < Bb * NG) {
        int j = idx & (NG - 1);
        g_gates[idx] = bih[j] + bhh[j];
    }
    // Wrw pack: 268 rows x 128 float4
    if (idx < NRW * 128) {
        int r = idx >> 7, f = idx & 127;
        ((float4*)g_Wrw)[idx] = r4((r < 70) ? Wr[idx] : Ww[(r - 70) * 128 + f]);
    }
    // g_rw bias init: Bb x NRW
    if (idx < Bb * NRW) {
        int j = idx % NRW;
        g_rw[idx] = (j < 70) ? br[j] : bw[j - 70];
    }
    // o_out bias init: Bb x 256
    if (idx < Bb * 256) {
        o_out[idx] = bo[idx & 255];
    }
    // A1 concat: Bb rows x 208 float4 (64 x | 16 prev_read | 128 h)
    if (idx < Bb * 208) {
        int b = idx / 208, f = idx - b * 208;
        float4 v;
        if (f < 64)      v = x[b * 64 + f];
        else if (f < 80) v = prev_read[b * 16 + (f - 64)];
        else             v = h[b * 128 + (f - 80)];
        ((float4*)g_A1)[idx] = r4(v);
    }
    // Wo rounded copy: 256 rows x 144 float4
    if (idx < 256 * 144) {
        ((float4*)g_Wo)[idx] = r4(Wo[idx]);
    }
}

// ------------------------- tf32 tensor-core GEMM (cp.async, split-K) --------
// C += A[M,K] @ W[N,K]^T  over K-range [z*Ksub, (z+1)*Ksub), atomic epilogue.
// C must be pre-initialized with bias.  tile 64x64, 256 threads (8 warps),
// BK=16, 4-stage cp.async.  A and W PRE-ROUNDED to tf32.  M%64==0, Ksub%16==0.

#define STAGES 4
#define STAGE_BYTES 5120   // 64*20*4

__device__ __forceinline__ void mma_tf32(float* c, const uint32_t* a,
                                         uint32_t b0, uint32_t b1) {
    asm volatile(
        "mma.sync.aligned.m16n8k8.row.col.f32.tf32.tf32.f32 "
        "{%0,%1,%2,%3}, {%4,%5,%6,%7}, {%8,%9}, {%0,%1,%2,%3};\n"
        : "+f"(c[0]), "+f"(c[1]), "+f"(c[2]), "+f"(c[3])
        : "r"(a[0]), "r"(a[1]), "r"(a[2]), "r"(a[3]), "r"(b0), "r"(b1));
}

__device__ __forceinline__ void cp16(uint32_t dst, const float* src, int sz) {
    asm volatile("cp.async.ca.shared.global [%0], [%1], 16, %2;\n"
                 :: "r"(dst), "l"(src), "r"(sz));
}

__global__ void __launch_bounds__(256, 2)
gemm_tf32(const float* __restrict__ A, const float* __restrict__ W,
          float* __restrict__ C, int M, int N, int K, int Ksub) {
    __shared__ float As[STAGES][64][20];
    __shared__ float Bs[STAGES][64][20];
    int bm = blockIdx.y * 64, bn = blockIdx.x * 64;
    int kOff = blockIdx.z * Ksub;
    int tid = threadIdx.x;
    int wid = tid >> 5, lane = tid & 31;
    int wm = (wid & 1) * 32, wn = (wid >> 1) * 16;
    int gid = lane >> 2, tig = lane & 3;

    int r = tid >> 2;            // 0..63
    int c4 = (tid & 3) << 2;     // 0,4,8,12
    const float* Ap = A + (size_t)(bm + r) * K + kOff + c4;
    bool wvalid = (bn + r) < N;
    int wsz = wvalid ? 16 : 0;
    const float* Wp = W + (size_t)(wvalid ? (bn + r) : 0) * K + kOff + c4;

    uint32_t aDst = (uint32_t)__cvta_generic_to_shared(&As[0][r][c4]);
    uint32_t bDst = (uint32_t)__cvta_generic_to_shared(&Bs[0][r][c4]);

    float acc[2][2][4];
#pragma unroll
    for (int i = 0; i < 2; i++)
#pragma unroll
        for (int j = 0; j < 2; j++)
#pragma unroll
            for (int q = 0; q < 4; q++) acc[i][j][q] = 0.f;

    int numK = Ksub >> 4;

#pragma unroll
    for (int s = 0; s < STAGES - 1; s++) {
        if (s < numK) {
            cp16(aDst + s * STAGE_BYTES, Ap + s * 16, 16);
            cp16(bDst + s * STAGE_BYTES, Wp + s * 16, wsz);
        }
        asm volatile("cp.async.commit_group;\n");
    }

    for (int kt = 0; kt < numK; kt++) {
        asm volatile("cp.async.wait_group %0;\n" :: "n"(STAGES - 2));
        __syncthreads();

        int kn = kt + STAGES - 1;
        if (kn < numK) {
            int s = kn & (STAGES - 1);
            cp16(aDst + s * STAGE_BYTES, Ap + kn * 16, 16);
            cp16(bDst + s * STAGE_BYTES, Wp + kn * 16, wsz);
        }
        asm volatile("cp.async.commit_group;\n");

        int st = kt & (STAGES - 1);
#pragma unroll
        for (int kk = 0; kk < 16; kk += 8) {
            uint32_t af[2][4];
#pragma unroll
            for (int i = 0; i < 2; i++) {
                int r0 = wm + i * 16 + gid;
                af[i][0] = __float_as_uint(As[st][r0][kk + tig]);
                af[i][1] = __float_as_uint(As[st][r0 + 8][kk + tig]);
                af[i][2] = __float_as_uint(As[st][r0][kk + tig + 4]);
                af[i][3] = __float_as_uint(As[st][r0 + 8][kk + tig + 4]);
            }
#pragma unroll
            for (int j = 0; j < 2; j++) {
                int c0 = wn + j * 8 + gid;
                uint32_t b0 = __float_as_uint(Bs[st][c0][kk + tig]);
                uint32_t b1 = __float_as_uint(Bs[st][c0][kk + tig + 4]);
#pragma unroll
                for (int i = 0; i < 2; i++) mma_tf32(acc[i][j], af[i], b0, b1);
            }
        }
    }

#pragma unroll
    for (int i = 0; i < 2; i++) {
        int row = bm + wm + i * 16 + gid;
#pragma unroll
        for (int j = 0; j < 2; j++) {
            int col = bn + wn + j * 8 + tig * 2;
            if (col < N) {
                atomicAdd(&C[(size_t)row * N + col],           acc[i][j][0]);
                atomicAdd(&C[(size_t)row * N + col + 1],       acc[i][j][1]);
                atomicAdd(&C[(size_t)(row + 8) * N + col],     acc[i][j][2]);
                atomicAdd(&C[(size_t)(row + 8) * N + col + 1], acc[i][j][3]);
            }
        }
    }
}

// ------------------------- LSTM pointwise (float4) ---------------------------

__global__ void lstm_pw(const float4* __restrict__ c_in,
                        float4* __restrict__ h_out, float4* __restrict__ c_out) {
    int idx = blockIdx.x * blockDim.x + threadIdx.x;
    if (idx >= Bb * CS / 4) return;
    int b = idx >> 7, q = idx & 127;
    const float* g = g_gates + (size_t)b * NG + q * 4;
    float4 i4 = *(const float4*)(g);
    float4 f4 = *(const float4*)(g + 512);
    float4 g4 = *(const float4*)(g + 1024);
    float4 o4 = *(const float4*)(g + 1536);
    float4 cv = c_in[idx];
    float4 cn, hn;
    cn.x = sigm(f4.x) * cv.x + sigm(i4.x) * ftanh(g4.x);
    cn.y = sigm(f4.y) * cv.y + sigm(i4.y) * ftanh(g4.y);
    cn.z = sigm(f4.z) * cv.z + sigm(i4.z) * ftanh(g4.z);
    cn.w = sigm(f4.w) * cv.w + sigm(i4.w) * ftanh(g4.w);
    hn.x = sigm(o4.x) * ftanh(cn.x);
    hn.y = sigm(o4.y) * ftanh(cn.y);
    hn.z = sigm(o4.z) * ftanh(cn.z);
    hn.w = sigm(o4.w) * ftanh(cn.w);
    c_out[idx] = cn;
    h_out[idx] = hn;
    ((float4*)g_h32)[idx] = r4(hn);   // tf32-rounded copy (addr GEMM A, A2 head)
}

// ------------------------- block reductions (512 threads, 16 warps) ----------

__device__ __forceinline__ float bred_max(float v, float* s16) {
#pragma unroll
    for (int off = 16; off; off >>= 1)
        v = fmaxf(v, __shfl_xor_sync(0xffffffffu, v, off));
    int wid = threadIdx.x >> 5, lane = threadIdx.x & 31;
    if (lane == 0) s16[wid] = v;
    __syncthreads();
    if (wid == 0) {
        float x = (lane < 16) ? s16[lane] : -1e30f;
#pragma unroll
        for (int off = 8; off; off >>= 1)
            x = fmaxf(x, __shfl_xor_sync(0xffffffffu, x, off));
        if (lane == 0) s16[0] = x;
    }
    __syncthreads();
    float r = s16[0];
    __syncthreads();
    return r;
}

__device__ __forceinline__ float bred_sum(float v, float* s16) {
#pragma unroll
    for (int off = 16; off; off >>= 1)
        v += __shfl_xor_sync(0xffffffffu, v, off);
    int wid = threadIdx.x >> 5, lane = threadIdx.x & 31;
    if (lane == 0) s16[wid] = v;
    __syncthreads();
    if (wid == 0) {
        float x = (lane < 16) ? s16[lane] : 0.f;
#pragma unroll
        for (int off = 8; off; off >>= 1)
            x += __shfl_xor_sync(0xffffffffu, x, off);
        if (lane == 0) s16[0] = x;
    }
    __syncthreads();
    float r = s16[0];
    __syncthreads();
    return r;
}

// ------------------------- fused memory pass ---------------------------------
// One CTA per batch element (grid=256, block=512).
//   pass 1: sim (dot + norms) for both heads   (reads memory[b], 512 KB)
//   phase 2: addressing (softmax/interp/shift/sharpen) both heads, in smem
//   pass 3: memory update + read_vec           (re-reads memory[b] — L2 hot)
//   epilogue: read_vec (no atomics), A2 row = [tf32(h_new) | tf32(read_vec)]

__global__ void __launch_bounds__(512, 2)
fused_mem(const float* __restrict__ mem,
          const float* __restrict__ read_w_prev,
          const float* __restrict__ write_w_prev,
          float* __restrict__ mem_out,
          float* __restrict__ w_read_out,
          float* __restrict__ w_write_out,
          float* __restrict__ read_vec) {
    __shared__ float s_simr[Nn], s_simw[Nn], s_wg[Nn];
    __shared__ float s_kr[64], s_kw[64], s_er[64], s_ad[64];
    __shared__ float s_par[2][6];   // beta, g, e0, e1, e2, gamma
    __shared__ float s_nrm[2];
    __shared__ float s_red[16];

    int b = blockIdx.x;
    int t = threadIdx.x;
    const float* base = g_rw + (size_t)b * NRW;

    // phase 0: keys / erase / add / scalar params
    if (t < 64)        s_kr[t] = base[t];
    else if (t < 128)  s_kw[t - 64] = base[70 + (t - 64)];
    else if (t < 192)  s_er[t - 128] = sigm(base[140 + (t - 128)]);
    else if (t < 256)  s_ad[t - 192] = base[204 + (t - 192)];
    else if (t < 258) {
        int head = t - 256;
        const float* ov = base + head * 70;
        float beta = softplus(ov[64]);
        float gg = sigm(ov[65]);
        float s0 = ov[66], s1 = ov[67], s2 = ov[68];
        float sm = fmaxf(s0, fmaxf(s1, s2));
        float e0 = __expf(s0 - sm), e1 = __expf(s1 - sm), e2 = __expf(s2 - sm);
        float es = e0 + e1 + e2;
        s_par[head][0] = beta; s_par[head][1] = gg;
        s_par[head][2] = e0 / es; s_par[head][3] = e1 / es; s_par[head][4] = e2 / es;
        s_par[head][5] = 1.f + softplus(ov[69]);
    }
    __syncthreads();

    int wid = t >> 5, lane = t & 31;
    if (wid < 2) {   // key norms
        const float* k = wid ? s_kw : s_kr;
        float s = k[lane] * k[lane] + k[lane + 32] * k[lane + 32];
#pragma unroll
        for (int off = 16; off; off >>= 1) s += __shfl_xor_sync(0xffffffffu, s, off);
        if (lane == 0) s_nrm[wid] = sqrtf(s) + 1e-8f;
    }
    __syncthreads();

    int g = t >> 3, l = t & 7;   // 64 groups of 8 lanes; lane owns cols l*8..l*8+7
    float krf[8], kwf[8], erf[8], adf[8];
#pragma unroll
    for (int j = 0; j < 8; j++) {
        krf[j] = s_kr[l * 8 + j]; kwf[j] = s_kw[l * 8 + j];
        erf[j] = s_er[l * 8 + j]; adf[j] = s_ad[l * 8 + j];
    }
    float nrmr = s_nrm[0], nrmw = s_nrm[1];

    const float* mrow = mem + ((size_t)b * Nn) * 64 + l * 8;

    // pass 1: similarity
#pragma unroll 2
    for (int i = 0; i < 32; i++) {
        int n = i * 64 + g;
        const float* p = mrow + (size_t)n * 64;
        float4 m0 = *(const float4*)p;
        float4 m1 = *(const float4*)(p + 4);
        float m[8] = {m0.x, m0.y, m0.z, m0.w, m1.x, m1.y, m1.z, m1.w};
        float dr = 0.f, dw = 0.f, sq = 0.f;
#pragma unroll
        for (int j = 0; j < 8; j++) {
            dr += m[j] * krf[j]; dw += m[j] * kwf[j]; sq += m[j] * m[j];
        }
#pragma unroll
        for (int off = 4; off; off >>= 1) {
            dr += __shfl_xor_sync(0xffffffffu, dr, off);
            dw += __shfl_xor_sync(0xffffffffu, dw, off);
            sq += __shfl_xor_sync(0xffffffffu, sq, off);
        }
        if (l == 0) {
            float nm = sqrtf(sq) + 1e-8f;
            s_simr[n] = dr / (nrmr * nm);
            s_simw[n] = dw / (nrmw * nm);
        }
    }
    __syncthreads();

    // phase 2: addressing, both heads (sim arrays end up holding final w)
    for (int head = 0; head < 2; head++) {
        float* sim = head ? s_simw : s_simr;
        const float* prevg = (head ? write_w_prev : read_w_prev) + (size_t)b * Nn;
        float* wout = (head ? w_write_out : w_read_out) + (size_t)b * Nn;
        float beta = s_par[head][0], gg = s_par[head][1];
        float e0 = s_par[head][2], e1 = s_par[head][3], e2 = s_par[head][4];
        float gamma = s_par[head][5];

        float loc[4];
        float mx = -1e30f;
#pragma unroll
        for (int i = 0; i < 4; i++) {
            float v = beta * sim[t + i * 512];
            loc[i] = v;
            mx = fmaxf(mx, v);
        }
        mx = bred_max(mx, s_red);
        float sum = 0.f;
#pragma unroll
        for (int i = 0; i < 4; i++) { loc[i] = __expf(loc[i] - mx); sum += loc[i]; }
        sum = bred_sum(sum, s_red);
        float inv = 1.f / sum;
#pragma unroll
        for (int i = 0; i < 4; i++) {
            int n = t + i * 512;
            s_wg[n] = gg * loc[i] * inv + (1.f - gg) * prevg[n];
        }
        __syncthreads();
        float ws[4];
        float sum2 = 0.f;
#pragma unroll
        for (int i = 0; i < 4; i++) {
            int n = t + i * 512;
            float v = e0 * s_wg[(n + Nn - 1) & (Nn - 1)] + e1 * s_wg[n]
                    + e2 * s_wg[(n + 1) & (Nn - 1)];
            v = __powf(v, gamma);
            ws[i] = v;
            sum2 += v;
        }
        sum2 = bred_sum(sum2, s_red);
        float inv2 = 1.f / (sum2 + 1e-8f);
#pragma unroll
        for (int i = 0; i < 4; i++) {
            int n = t + i * 512;
            float w = ws[i] * inv2;
            wout[n] = w;
            sim[n] = w;   // keep for update pass
        }
        __syncthreads();
    }

    // pass 3: memory update + read_vec accumulation
    float rv[8];
#pragma unroll
    for (int j = 0; j < 8; j++) rv[j] = 0.f;
    float* orow = mem_out + ((size_t)b * Nn) * 64 + l * 8;
#pragma unroll 2
    for (int i = 0; i < 32; i++) {
        int n = i * 64 + g;
        float wr = s_simr[n], ww = s_simw[n];
        const float* p = mrow + (size_t)n * 64;
        float4 m0 = *(const float4*)p;
        float4 m1 = *(const float4*)(p + 4);
        float m[8] = {m0.x, m0.y, m0.z, m0.w, m1.x, m1.y, m1.z, m1.w};
        float o[8];
#pragma unroll
        for (int j = 0; j < 8; j++) {
            o[j] = m[j] * (1.f - ww * erf[j]) + ww * adf[j];
            rv[j] += wr * m[j];
        }
        float* q = orow + (size_t)n * 64;
        *(float4*)q       = make_float4(o[0], o[1], o[2], o[3]);
        *(float4*)(q + 4) = make_float4(o[4], o[5], o[6], o[7]);
    }
    __syncthreads();

    // read_vec reduction: group g holds partials for cols l*8..l*8+7
    float* part = (g < 32) ? &s_simr[g * 64] : &s_simw[(g - 32) * 64];
#pragma unroll
    for (int j = 0; j < 8; j++) part[l * 8 + j] = rv[j];
    // A2 head: tf32(h_new) — g_h32 is already rounded
    g_A2[(size_t)b * KO + t] = g_h32[(size_t)b * CS + t];
    __syncthreads();
    if (t < 64) {
        float s = 0.f;
#pragma unroll 8
        for (int g2 = 0; g2 < 32; g2++) s += s_simr[g2 * 64 + t];
#pragma unroll 8
        for (int g2 = 0; g2 < 32; g2++) s += s_simw[g2 * 64 + t];
        read_vec[(size_t)b * Mm + t] = s;
        g_A2[(size_t)b * KO + CS + t] = to_tf32(s);
    }
}

// ---------------------------------------------------------------------------

extern "C" void kernel_launch(void* const* d_in, const int* in_sizes, int n_in,
                              void* d_out, int out_size) {
    const float* x         = (const float*)d_in[0];
    const float* memory    = (const float*)d_in[1];
    const float* h         = (const float*)d_in[2];
    const float* c         = (const float*)d_in[3];
    const float* read_w    = (const float*)d_in[4];
    const float* write_w   = (const float*)d_in[5];
    const float* prev_read = (const float*)d_in[6];
    const float* W_ih      = (const float*)d_in[7];
    const float* W_hh      = (const float*)d_in[8];
    const float* b_ih      = (const float*)d_in[9];
    const float* b_hh      = (const float*)d_in[10];
    const float* W_r       = (const float*)d_in[11];
    const float* b_r       = (const float*)d_in[12];
    const float* W_w       = (const float*)d_in[13];
    const float* b_w       = (const float*)d_in[14];
    const float* W_o       = (const float*)d_in[15];
    const float* b_o       = (const float*)d_in[16];

    float* out  = (float*)d_out;
    float* o_out = out + OFF_OUT;
    float* o_mem = out + OFF_MEM;
    float* o_h   = out + OFF_H;
    float* o_c   = out + OFF_C;
    float* o_wr  = out + OFF_WR;
    float* o_ww  = out + OFF_WW;
    float* o_rv  = out + OFF_RV;

    float *A1, *Wg, *gates, *Wrw, *A2, *rw, *Wo, *h32;
    cudaGetSymbolAddress((void**)&A1,    g_A1);
    cudaGetSymbolAddress((void**)&Wg,    g_Wg);
    cudaGetSymbolAddress((void**)&gates, g_gates);
    cudaGetSymbolAddress((void**)&Wrw,   g_Wrw);
    cudaGetSymbolAddress((void**)&A2,    g_A2);
    cudaGetSymbolAddress((void**)&rw,    g_rw);
    cudaGetSymbolAddress((void**)&Wo,    g_Wo);
    cudaGetSymbolAddress((void**)&h32,   g_h32);

    // 1. weight packing + input concat + bias-init of accumulators
    prep_all<<<(Bb * NG + 255) / 256, 256>>>(
        (const float4*)W_ih, (const float4*)W_hh, b_ih, b_hh,
        (const float4*)W_r, b_r, (const float4*)W_w, b_w,
        (const float4*)x, (const float4*)prev_read, (const float4*)h,
        (const float4*)W_o, b_o, o_out);
    // 2. gates GEMM  [256,832] x [2048,832]^T  split-K=2 -> 256 CTAs
    gemm_tf32<<<dim3(NG / 64, Bb / 64, 2), 256>>>(A1, Wg, gates, Bb, NG, KG, KG / 2);
    // 3. LSTM pointwise -> h_new, c_new (+ rounded h copy)
    lstm_pw<<<(Bb * CS / 4 + 255) / 256, 256>>>((const float4*)c,
                                                (float4*)o_h, (float4*)o_c);
    // 4. addressing GEMM  h_new x [268,512]^T  split-K=4 -> 80 CTAs
    gemm_tf32<<<dim3((NRW + 63) / 64, Bb / 64, 4), 256>>>(h32, Wrw, rw, Bb, NRW, CS, CS / 4);
    // 5. fused sim + addressing + update + read_vec + A2 concat
    fused_mem<<<Bb, 512>>>(memory, read_w, write_w, o_mem, o_wr, o_ww, o_rv);
    // 6. output GEMM  split-K=4 -> 64 CTAs
    gemm_tf32<<<dim3(256 / 64, Bb / 64, 4), 256>>>(A2, Wo, o_out, Bb, 256, KO, KO / 4);
}

// round 12
// speedup vs baseline: 3.0065x; 1.0024x over previous
#include <cuda_runtime.h>
#include <cstdint>
#include <cstddef>

// ---------------------------------------------------------------------------
// NTM single step.  B=256, N=2048, M=64, CS=512, INP=256, OUT=256
// ---------------------------------------------------------------------------

#define Bb 256
#define Nn 2048
#define Mm 64
#define CS 512
#define KG 832      // INP + M + CS
#define NG 2048     // 4*CS
#define NRW 268     // ADDR_R(70) + ADDR_W(198)
#define KO 576      // CS + M

// output offsets (elements)
#define OFF_OUT 0
#define OFF_MEM 65536
#define OFF_H   33619968
#define OFF_C   33751040
#define OFF_WR  33882112
#define OFF_WW  34406400
#define OFF_RV  34930688

// scratch (all GEMM operands pre-rounded to tf32 by producers)
__device__ float g_A1[Bb * KG];
__device__ float g_Wg[NG * KG];
__device__ float g_gates[Bb * NG];
__device__ float g_Wrw[NRW * CS];
__device__ float g_rw[Bb * NRW];
__device__ float g_A2[Bb * KO];
__device__ float g_Wo[256 * KO];
__device__ float g_h32[Bb * CS];

__device__ __forceinline__ float sigm(float x) { return 1.f / (1.f + __expf(-x)); }
__device__ __forceinline__ float ftanh(float x) {
    float e = __expf(2.f * x);
    return (e - 1.f) / (e + 1.f);
}
__device__ __forceinline__ float softplus(float x) { return x > 20.f ? x : log1pf(expf(x)); }
__device__ __forceinline__ float to_tf32(float x) {
    float r; asm("cvt.rna.tf32.f32 %0, %1;" : "=f"(r) : "f"(x)); return r;
}
__device__ __forceinline__ float4 r4(float4 v) {
    return make_float4(to_tf32(v.x), to_tf32(v.y), to_tf32(v.z), to_tf32(v.w));
}

// ------------------------- combined prep (float4, tf32-rounded) --------------

__global__ void prep_all(const float4* __restrict__ Wih, const float4* __restrict__ Whh,
                         const float* __restrict__ bih, const float* __restrict__ bhh,
                         const float4* __restrict__ Wr,  const float* __restrict__ br,
                         const float4* __restrict__ Ww,  const float* __restrict__ bw,
                         const float4* __restrict__ x,   const float4* __restrict__ prev_read,
                         const float4* __restrict__ h,   const float4* __restrict__ Wo,
                         const float* __restrict__ bo,   float* __restrict__ o_out) {
    int idx = blockIdx.x * blockDim.x + threadIdx.x;
    if (idx < NG * 208) {
        int n = idx / 208, f = idx - n * 208;
        ((float4*)g_Wg)[idx] = r4((f < 80) ? Wih[n * 80 + f] : Whh[n * 128 + (f - 80)]);
    }
    if (idx < Bb * NG) {
        int j = idx & (NG - 1);
        g_gates[idx] = bih[j] + bhh[j];
    }
    if (idx < NRW * 128) {
        int r = idx >> 7, f = idx & 127;
        ((float4*)g_Wrw)[idx] = r4((r < 70) ? Wr[idx] : Ww[(r - 70) * 128 + f]);
    }
    if (idx < Bb * NRW) {
        int j = idx % NRW;
        g_rw[idx] = (j < 70) ? br[j] : bw[j - 70];
    }
    if (idx < Bb * 256) {
        o_out[idx] = bo[idx & 255];
    }
    if (idx < Bb * 208) {
        int b = idx / 208, f = idx - b * 208;
        float4 v;
        if (f < 64)      v = x[b * 64 + f];
        else if (f < 80) v = prev_read[b * 16 + (f - 64)];
        else             v = h[b * 128 + (f - 80)];
        ((float4*)g_A1)[idx] = r4(v);
    }
    if (idx < 256 * 144) {
        ((float4*)g_Wo)[idx] = r4(Wo[idx]);
    }
}

// ------------------------- tf32 tensor-core GEMM (cp.async, split-K) --------

#define STAGES 4
#define STAGE_BYTES 5120   // 64*20*4

__device__ __forceinline__ void mma_tf32(float* c, const uint32_t* a,
                                         uint32_t b0, uint32_t b1) {
    asm volatile(
        "mma.sync.aligned.m16n8k8.row.col.f32.tf32.tf32.f32 "
        "{%0,%1,%2,%3}, {%4,%5,%6,%7}, {%8,%9}, {%0,%1,%2,%3};\n"
        : "+f"(c[0]), "+f"(c[1]), "+f"(c[2]), "+f"(c[3])
        : "r"(a[0]), "r"(a[1]), "r"(a[2]), "r"(a[3]), "r"(b0), "r"(b1));
}

__device__ __forceinline__ void cp16(uint32_t dst, const float* src, int sz) {
    asm volatile("cp.async.ca.shared.global [%0], [%1], 16, %2;\n"
                 :: "r"(dst), "l"(src), "r"(sz));
}

__global__ void __launch_bounds__(256, 2)
gemm_tf32(const float* __restrict__ A, const float* __restrict__ W,
          float* __restrict__ C, int M, int N, int K, int Ksub) {
    __shared__ float As[STAGES][64][20];
    __shared__ float Bs[STAGES][64][20];
    int bm = blockIdx.y * 64, bn = blockIdx.x * 64;
    int kOff = blockIdx.z * Ksub;
    int tid = threadIdx.x;
    int wid = tid >> 5, lane = tid & 31;
    int wm = (wid & 1) * 32, wn = (wid >> 1) * 16;
    int gid = lane >> 2, tig = lane & 3;

    int r = tid >> 2;
    int c4 = (tid & 3) << 2;
    const float* Ap = A + (size_t)(bm + r) * K + kOff + c4;
    bool wvalid = (bn + r) < N;
    int wsz = wvalid ? 16 : 0;
    const float* Wp = W + (size_t)(wvalid ? (bn + r) : 0) * K + kOff + c4;

    uint32_t aDst = (uint32_t)__cvta_generic_to_shared(&As[0][r][c4]);
    uint32_t bDst = (uint32_t)__cvta_generic_to_shared(&Bs[0][r][c4]);

    float acc[2][2][4];
#pragma unroll
    for (int i = 0; i < 2; i++)
#pragma unroll
        for (int j = 0; j < 2; j++)
#pragma unroll
            for (int q = 0; q < 4; q++) acc[i][j][q] = 0.f;

    int numK = Ksub >> 4;

#pragma unroll
    for (int s = 0; s < STAGES - 1; s++) {
        if (s < numK) {
            cp16(aDst + s * STAGE_BYTES, Ap + s * 16, 16);
            cp16(bDst + s * STAGE_BYTES, Wp + s * 16, wsz);
        }
        asm volatile("cp.async.commit_group;\n");
    }

    for (int kt = 0; kt < numK; kt++) {
        asm volatile("cp.async.wait_group %0;\n" :: "n"(STAGES - 2));
        __syncthreads();

        int kn = kt + STAGES - 1;
        if (kn < numK) {
            int s = kn & (STAGES - 1);
            cp16(aDst + s * STAGE_BYTES, Ap + kn * 16, 16);
            cp16(bDst + s * STAGE_BYTES, Wp + kn * 16, wsz);
        }
        asm volatile("cp.async.commit_group;\n");

        int st = kt & (STAGES - 1);
#pragma unroll
        for (int kk = 0; kk < 16; kk += 8) {
            uint32_t af[2][4];
#pragma unroll
            for (int i = 0; i < 2; i++) {
                int r0 = wm + i * 16 + gid;
                af[i][0] = __float_as_uint(As[st][r0][kk + tig]);
                af[i][1] = __float_as_uint(As[st][r0 + 8][kk + tig]);
                af[i][2] = __float_as_uint(As[st][r0][kk + tig + 4]);
                af[i][3] = __float_as_uint(As[st][r0 + 8][kk + tig + 4]);
            }
#pragma unroll
            for (int j = 0; j < 2; j++) {
                int c0 = wn + j * 8 + gid;
                uint32_t b0 = __float_as_uint(Bs[st][c0][kk + tig]);
                uint32_t b1 = __float_as_uint(Bs[st][c0][kk + tig + 4]);
#pragma unroll
                for (int i = 0; i < 2; i++) mma_tf32(acc[i][j], af[i], b0, b1);
            }
        }
    }

#pragma unroll
    for (int i = 0; i < 2; i++) {
        int row = bm + wm + i * 16 + gid;
#pragma unroll
        for (int j = 0; j < 2; j++) {
            int col = bn + wn + j * 8 + tig * 2;
            if (col < N) {
                atomicAdd(&C[(size_t)row * N + col],           acc[i][j][0]);
                atomicAdd(&C[(size_t)row * N + col + 1],       acc[i][j][1]);
                atomicAdd(&C[(size_t)(row + 8) * N + col],     acc[i][j][2]);
                atomicAdd(&C[(size_t)(row + 8) * N + col + 1], acc[i][j][3]);
            }
        }
    }
}

// ------------------------- LSTM pointwise (float4) ---------------------------

__global__ void lstm_pw(const float4* __restrict__ c_in,
                        float4* __restrict__ h_out, float4* __restrict__ c_out) {
    int idx = blockIdx.x * blockDim.x + threadIdx.x;
    if (idx >= Bb * CS / 4) return;
    int b = idx >> 7, q = idx & 127;
    const float* g = g_gates + (size_t)b * NG + q * 4;
    float4 i4 = *(const float4*)(g);
    float4 f4 = *(const float4*)(g + 512);
    float4 g4 = *(const float4*)(g + 1024);
    float4 o4 = *(const float4*)(g + 1536);
    float4 cv = c_in[idx];
    float4 cn, hn;
    cn.x = sigm(f4.x) * cv.x + sigm(i4.x) * ftanh(g4.x);
    cn.y = sigm(f4.y) * cv.y + sigm(i4.y) * ftanh(g4.y);
    cn.z = sigm(f4.z) * cv.z + sigm(i4.z) * ftanh(g4.z);
    cn.w = sigm(f4.w) * cv.w + sigm(i4.w) * ftanh(g4.w);
    hn.x = sigm(o4.x) * ftanh(cn.x);
    hn.y = sigm(o4.y) * ftanh(cn.y);
    hn.z = sigm(o4.z) * ftanh(cn.z);
    hn.w = sigm(o4.w) * ftanh(cn.w);
    c_out[idx] = cn;
    h_out[idx] = hn;
    ((float4*)g_h32)[idx] = r4(hn);
}

// ------------------------- block reductions (512 threads, 16 warps) ----------

__device__ __forceinline__ float bred_max(float v, float* s16) {
#pragma unroll
    for (int off = 16; off; off >>= 1)
        v = fmaxf(v, __shfl_xor_sync(0xffffffffu, v, off));
    int wid = threadIdx.x >> 5, lane = threadIdx.x & 31;
    if (lane == 0) s16[wid] = v;
    __syncthreads();
    if (wid == 0) {
        float x = (lane < 16) ? s16[lane] : -1e30f;
#pragma unroll
        for (int off = 8; off; off >>= 1)
            x = fmaxf(x, __shfl_xor_sync(0xffffffffu, x, off));
        if (lane == 0) s16[0] = x;
    }
    __syncthreads();
    float r = s16[0];
    __syncthreads();
    return r;
}

__device__ __forceinline__ float bred_sum(float v, float* s16) {
#pragma unroll
    for (int off = 16; off; off >>= 1)
        v += __shfl_xor_sync(0xffffffffu, v, off);
    int wid = threadIdx.x >> 5, lane = threadIdx.x & 31;
    if (lane == 0) s16[wid] = v;
    __syncthreads();
    if (wid == 0) {
        float x = (lane < 16) ? s16[lane] : 0.f;
#pragma unroll
        for (int off = 8; off; off >>= 1)
            x += __shfl_xor_sync(0xffffffffu, x, off);
        if (lane == 0) s16[0] = x;
    }
    __syncthreads();
    float r = s16[0];
    __syncthreads();
    return r;
}

// ------------------------- fused memory pass ---------------------------------
// One CTA per batch element (grid=256, block=512).  Pass 3 runs in REVERSE
// order (tail lines are L2-freshest from pass 1) with streaming hints
// (__ldcs on the one-shot re-read, __stcs on the write) to avoid evicting
// reusable lines.

__global__ void __launch_bounds__(512, 2)
fused_mem(const float* __restrict__ mem,
          const float* __restrict__ read_w_prev,
          const float* __restrict__ write_w_prev,
          float* __restrict__ mem_out,
          float* __restrict__ w_read_out,
          float* __restrict__ w_write_out,
          float* __restrict__ read_vec) {
    __shared__ float s_simr[Nn], s_simw[Nn], s_wg[Nn];
    __shared__ float s_kr[64], s_kw[64], s_er[64], s_ad[64];
    __shared__ float s_par[2][6];
    __shared__ float s_nrm[2];
    __shared__ float s_red[16];

    int b = blockIdx.x;
    int t = threadIdx.x;
    const float* base = g_rw + (size_t)b * NRW;

    if (t < 64)        s_kr[t] = base[t];
    else if (t < 128)  s_kw[t - 64] = base[70 + (t - 64)];
    else if (t < 192)  s_er[t - 128] = sigm(base[140 + (t - 128)]);
    else if (t < 256)  s_ad[t - 192] = base[204 + (t - 192)];
    else if (t < 258) {
        int head = t - 256;
        const float* ov = base + head * 70;
        float beta = softplus(ov[64]);
        float gg = sigm(ov[65]);
        float s0 = ov[66], s1 = ov[67], s2 = ov[68];
        float sm = fmaxf(s0, fmaxf(s1, s2));
        float e0 = __expf(s0 - sm), e1 = __expf(s1 - sm), e2 = __expf(s2 - sm);
        float es = e0 + e1 + e2;
        s_par[head][0] = beta; s_par[head][1] = gg;
        s_par[head][2] = e0 / es; s_par[head][3] = e1 / es; s_par[head][4] = e2 / es;
        s_par[head][5] = 1.f + softplus(ov[69]);
    }
    __syncthreads();

    int wid = t >> 5, lane = t & 31;
    if (wid < 2) {
        const float* k = wid ? s_kw : s_kr;
        float s = k[lane] * k[lane] + k[lane + 32] * k[lane + 32];
#pragma unroll
        for (int off = 16; off; off >>= 1) s += __shfl_xor_sync(0xffffffffu, s, off);
        if (lane == 0) s_nrm[wid] = sqrtf(s) + 1e-8f;
    }
    __syncthreads();

    int g = t >> 3, l = t & 7;
    float krf[8], kwf[8], erf[8], adf[8];
#pragma unroll
    for (int j = 0; j < 8; j++) {
        krf[j] = s_kr[l * 8 + j]; kwf[j] = s_kw[l * 8 + j];
        erf[j] = s_er[l * 8 + j]; adf[j] = s_ad[l * 8 + j];
    }
    float nrmr = s_nrm[0], nrmw = s_nrm[1];

    const float* mrow = mem + ((size_t)b * Nn) * 64 + l * 8;

    // pass 1: similarity (forward; default caching — lines reused in pass 3)
#pragma unroll 2
    for (int i = 0; i < 32; i++) {
        int n = i * 64 + g;
        const float* p = mrow + (size_t)n * 64;
        float4 m0 = *(const float4*)p;
        float4 m1 = *(const float4*)(p + 4);
        float m[8] = {m0.x, m0.y, m0.z, m0.w, m1.x, m1.y, m1.z, m1.w};
        float dr = 0.f, dw = 0.f, sq = 0.f;
#pragma unroll
        for (int j = 0; j < 8; j++) {
            dr += m[j] * krf[j]; dw += m[j] * kwf[j]; sq += m[j] * m[j];
        }
#pragma unroll
        for (int off = 4; off; off >>= 1) {
            dr += __shfl_xor_sync(0xffffffffu, dr, off);
            dw += __shfl_xor_sync(0xffffffffu, dw, off);
            sq += __shfl_xor_sync(0xffffffffu, sq, off);
        }
        if (l == 0) {
            float nm = sqrtf(sq) + 1e-8f;
            s_simr[n] = dr / (nrmr * nm);
            s_simw[n] = dw / (nrmw * nm);
        }
    }
    __syncthreads();

    // phase 2: addressing, both heads
    for (int head = 0; head < 2; head++) {
        float* sim = head ? s_simw : s_simr;
        const float* prevg = (head ? write_w_prev : read_w_prev) + (size_t)b * Nn;
        float* wout = (head ? w_write_out : w_read_out) + (size_t)b * Nn;
        float beta = s_par[head][0], gg = s_par[head][1];
        float e0 = s_par[head][2], e1 = s_par[head][3], e2 = s_par[head][4];
        float gamma = s_par[head][5];

        float loc[4];
        float mx = -1e30f;
#pragma unroll
        for (int i = 0; i < 4; i++) {
            float v = beta * sim[t + i * 512];
            loc[i] = v;
            mx = fmaxf(mx, v);
        }
        mx = bred_max(mx, s_red);
        float sum = 0.f;
#pragma unroll
        for (int i = 0; i < 4; i++) { loc[i] = __expf(loc[i] - mx); sum += loc[i]; }
        sum = bred_sum(sum, s_red);
        float inv = 1.f / sum;
#pragma unroll
        for (int i = 0; i < 4; i++) {
            int n = t + i * 512;
            s_wg[n] = gg * loc[i] * inv + (1.f - gg) * prevg[n];
        }
        __syncthreads();
        float ws[4];
        float sum2 = 0.f;
#pragma unroll
        for (int i = 0; i < 4; i++) {
            int n = t + i * 512;
            float v = e0 * s_wg[(n + Nn - 1) & (Nn - 1)] + e1 * s_wg[n]
                    + e2 * s_wg[(n + 1) & (Nn - 1)];
            v = __powf(v, gamma);
            ws[i] = v;
            sum2 += v;
        }
        sum2 = bred_sum(sum2, s_red);
        float inv2 = 1.f / (sum2 + 1e-8f);
#pragma unroll
        for (int i = 0; i < 4; i++) {
            int n = t + i * 512;
            float w = ws[i] * inv2;
            wout[n] = w;
            sim[n] = w;
        }
        __syncthreads();
    }

    // pass 3: memory update + read_vec (REVERSE order, streaming hints)
    float rv[8];
#pragma unroll
    for (int j = 0; j < 8; j++) rv[j] = 0.f;
    float* orow = mem_out + ((size_t)b * Nn) * 64 + l * 8;
#pragma unroll 2
    for (int i = 31; i >= 0; i--) {
        int n = i * 64 + g;
        float wr = s_simr[n], ww = s_simw[n];
        const float* p = mrow + (size_t)n * 64;
        float4 m0 = __ldcs((const float4*)p);
        float4 m1 = __ldcs((const float4*)(p + 4));
        float m[8] = {m0.x, m0.y, m0.z, m0.w, m1.x, m1.y, m1.z, m1.w};
        float o[8];
#pragma unroll
        for (int j = 0; j < 8; j++) {
            o[j] = m[j] * (1.f - ww * erf[j]) + ww * adf[j];
            rv[j] += wr * m[j];
        }
        float* q = orow + (size_t)n * 64;
        __stcs((float4*)q,       make_float4(o[0], o[1], o[2], o[3]));
        __stcs((float4*)(q + 4), make_float4(o[4], o[5], o[6], o[7]));
    }
    __syncthreads();

    float* part = (g < 32) ? &s_simr[g * 64] : &s_simw[(g - 32) * 64];
#pragma unroll
    for (int j = 0; j < 8; j++) part[l * 8 + j] = rv[j];
    g_A2[(size_t)b * KO + t] = g_h32[(size_t)b * CS + t];
    __syncthreads();
    if (t < 64) {
        float s = 0.f;
#pragma unroll 8
        for (int g2 = 0; g2 < 32; g2++) s += s_simr[g2 * 64 + t];
#pragma unroll 8
        for (int g2 = 0; g2 < 32; g2++) s += s_simw[g2 * 64 + t];
        read_vec[(size_t)b * Mm + t] = s;
        g_A2[(size_t)b * KO + CS + t] = to_tf32(s);
    }
}

// ---------------------------------------------------------------------------

extern "C" void kernel_launch(void* const* d_in, const int* in_sizes, int n_in,
                              void* d_out, int out_size) {
    const float* x         = (const float*)d_in[0];
    const float* memory    = (const float*)d_in[1];
    const float* h         = (const float*)d_in[2];
    const float* c         = (const float*)d_in[3];
    const float* read_w    = (const float*)d_in[4];
    const float* write_w   = (const float*)d_in[5];
    const float* prev_read = (const float*)d_in[6];
    const float* W_ih      = (const float*)d_in[7];
    const float* W_hh      = (const float*)d_in[8];
    const float* b_ih      = (const float*)d_in[9];
    const float* b_hh      = (const float*)d_in[10];
    const float* W_r       = (const float*)d_in[11];
    const float* b_r       = (const float*)d_in[12];
    const float* W_w       = (const float*)d_in[13];
    const float* b_w       = (const float*)d_in[14];
    const float* W_o       = (const float*)d_in[15];
    const float* b_o       = (const float*)d_in[16];

    float* out  = (float*)d_out;
    float* o_out = out + OFF_OUT;
    float* o_mem = out + OFF_MEM;
    float* o_h   = out + OFF_H;
    float* o_c   = out + OFF_C;
    float* o_wr  = out + OFF_WR;
    float* o_ww  = out + OFF_WW;
    float* o_rv  = out + OFF_RV;

    float *A1, *Wg, *gates, *Wrw, *A2, *rw, *Wo, *h32;
    cudaGetSymbolAddress((void**)&A1,    g_A1);
    cudaGetSymbolAddress((void**)&Wg,    g_Wg);
    cudaGetSymbolAddress((void**)&gates, g_gates);
    cudaGetSymbolAddress((void**)&Wrw,   g_Wrw);
    cudaGetSymbolAddress((void**)&A2,    g_A2);
    cudaGetSymbolAddress((void**)&rw,    g_rw);
    cudaGetSymbolAddress((void**)&Wo,    g_Wo);
    cudaGetSymbolAddress((void**)&h32,   g_h32);

    // 1. weight packing + input concat + bias-init of accumulators
    prep_all<<<(Bb * NG + 255) / 256, 256>>>(
        (const float4*)W_ih, (const float4*)W_hh, b_ih, b_hh,
        (const float4*)W_r, b_r, (const float4*)W_w, b_w,
        (const float4*)x, (const float4*)prev_read, (const float4*)h,
        (const float4*)W_o, b_o, o_out);
    // 2. gates GEMM  [256,832] x [2048,832]^T  split-K=4 -> 512 CTAs
    gemm_tf32<<<dim3(NG / 64, Bb / 64, 4), 256>>>(A1, Wg, gates, Bb, NG, KG, KG / 4);
    // 3. LSTM pointwise -> h_new, c_new (+ rounded h copy)
    lstm_pw<<<(Bb * CS / 4 + 255) / 256, 256>>>((const float4*)c,
                                                (float4*)o_h, (float4*)o_c);
    // 4. addressing GEMM  h_new x [268,512]^T  split-K=8 -> 160 CTAs
    gemm_tf32<<<dim3((NRW + 63) / 64, Bb / 64, 8), 256>>>(h32, Wrw, rw, Bb, NRW, CS, CS / 8);
    // 5. fused sim + addressing + update + read_vec + A2 concat
    fused_mem<<<Bb, 512>>>(memory, read_w, write_w, o_mem, o_wr, o_ww, o_rv);
    // 6. output GEMM  split-K=6 -> 96 CTAs
    gemm_tf32<<<dim3(256 / 64, Bb / 64, 6), 256>>>(A2, Wo, o_out, Bb, 256, KO, KO / 6);
}